// round 1
// baseline (speedup 1.0000x reference)
#include <cuda_runtime.h>
#include <math.h>

#define Bb 4
#define Ss 2048
#define Dd 768
#define Hh 12
#define Ee 64
#define BS (Bb*Ss)

// Scratch (device globals: allocation-free rule)
__device__ float g_q[Bb*Hh*Ss*Ee];     // [B,H,S,E]
__device__ float g_k[Bb*Hh*Ss*Ee];
__device__ float g_v[Bb*Hh*Ss*Ee];
__device__ float g_attn[Bb*Ss*Hh*Ee];  // [B,S,H*E]

// ---------------------------------------------------------------------------
// Kernel 1: fused QKV projection. grid(BS/64, H), 256 threads.
// Per block: 64 rows of x  x  [768x64] Wq/Wk/Wv (shared x tile => 3x reuse)
// ---------------------------------------------------------------------------
__global__ __launch_bounds__(256) void qkv_kernel(
    const float* __restrict__ x,
    const float* __restrict__ Wq, const float* __restrict__ bq,
    const float* __restrict__ Wk, const float* __restrict__ bk,
    const float* __restrict__ Wv, const float* __restrict__ bv)
{
    __shared__ float xs[64][33];
    __shared__ float wqs[32][64];
    __shared__ float wks[32][64];
    __shared__ float wvs[32][64];

    const int m0 = blockIdx.x * 64;
    const int h  = blockIdx.y;
    const float* wqp = Wq + h*Dd*Ee;
    const float* wkp = Wk + h*Dd*Ee;
    const float* wvp = Wv + h*Dd*Ee;
    const int tid = threadIdx.x;
    const int tx = tid & 15, ty = tid >> 4;

    float aq[4][4] = {}, ak[4][4] = {}, av[4][4] = {};

    for (int k0 = 0; k0 < Dd; k0 += 32) {
        #pragma unroll
        for (int i = 0; i < 8; i++) {
            int li = tid + i*256;
            int r = li >> 5, c = li & 31;
            xs[r][c] = x[(m0 + r)*Dd + k0 + c];
        }
        #pragma unroll
        for (int i = 0; i < 8; i++) {
            int li = tid + i*256;
            int r = li >> 6, c = li & 63;
            wqs[r][c] = wqp[(k0 + r)*Ee + c];
            wks[r][c] = wkp[(k0 + r)*Ee + c];
            wvs[r][c] = wvp[(k0 + r)*Ee + c];
        }
        __syncthreads();
        #pragma unroll
        for (int kk = 0; kk < 32; kk++) {
            float a[4], q4[4], k4[4], v4[4];
            #pragma unroll
            for (int i = 0; i < 4; i++) a[i] = xs[ty*4 + i][kk];
            #pragma unroll
            for (int j = 0; j < 4; j++) {
                q4[j] = wqs[kk][tx*4 + j];
                k4[j] = wks[kk][tx*4 + j];
                v4[j] = wvs[kk][tx*4 + j];
            }
            #pragma unroll
            for (int i = 0; i < 4; i++)
                #pragma unroll
                for (int j = 0; j < 4; j++) {
                    aq[i][j] += a[i]*q4[j];
                    ak[i][j] += a[i]*k4[j];
                    av[i][j] += a[i]*v4[j];
                }
        }
        __syncthreads();
    }

    #pragma unroll
    for (int i = 0; i < 4; i++) {
        int row = m0 + ty*4 + i;
        int b = row / Ss, s = row % Ss;
        int base = ((b*Hh + h)*Ss + s)*Ee;
        #pragma unroll
        for (int j = 0; j < 4; j++) {
            int e = tx*4 + j;
            g_q[base + e] = aq[i][j] + bq[h*Ee + e];
            g_k[base + e] = ak[i][j] + bk[h*Ee + e];
            g_v[base + e] = av[i][j] + bv[h*Ee + e];
        }
    }
}

// ---------------------------------------------------------------------------
// Kernel 2: flash attention. grid(S/64, H, B), 256 threads, dynamic smem.
// Each block: 64 query rows, streams 32 K/V tiles of 64 with online softmax.
// ---------------------------------------------------------------------------
__global__ __launch_bounds__(256) void attn_kernel()
{
    extern __shared__ float sm[];
    float* Qs   = sm;                // [64][65]  Q tile
    float* KsT  = Qs  + 64*65;       // [64 e][65 c] K tile transposed
    float* Vs   = KsT + 64*65;       // [64 kk][65 c] V tile
    float* sc   = Vs  + 64*65;       // [64][65]  scores / probabilities
    float* m_s  = sc  + 64*65;       // [64] running max
    float* l_s  = m_s + 64;          // [64] running sum
    float* al_s = l_s + 64;          // [64] rescale factor

    const int q0 = blockIdx.x * 64;
    const int h  = blockIdx.y;
    const int b  = blockIdx.z;
    const int tid = threadIdx.x;
    const int tx = tid & 15, ty = tid >> 4;
    const int bh = b*Hh + h;
    const float* qp = g_q + bh*Ss*Ee;
    const float* kp = g_k + bh*Ss*Ee;
    const float* vp = g_v + bh*Ss*Ee;

    #pragma unroll
    for (int i = 0; i < 16; i++) {
        int li = tid + i*256;
        int r = li >> 6, e = li & 63;
        Qs[r*65 + e] = qp[(q0 + r)*Ee + e];
    }
    if (tid < 64) { m_s[tid] = -1e30f; l_s[tid] = 0.f; }

    float o[4][4] = {};
    const float scale = 0.125f;   // 1/sqrt(64)

    for (int k0 = 0; k0 < Ss; k0 += 64) {
        __syncthreads();  // smem reuse from previous iter / Q-load + init fence
        #pragma unroll
        for (int i = 0; i < 16; i++) {
            int li = tid + i*256;
            int c = li >> 6, e = li & 63;
            KsT[e*65 + c] = kp[(k0 + c)*Ee + e];
            Vs[c*65 + e]  = vp[(k0 + c)*Ee + e];
        }
        __syncthreads();

        // scores: S = Q K^T * scale
        float acc[4][4] = {};
        #pragma unroll
        for (int e = 0; e < 64; e++) {
            float a[4], bb[4];
            #pragma unroll
            for (int i = 0; i < 4; i++) a[i] = Qs[(ty*4 + i)*65 + e];
            #pragma unroll
            for (int j = 0; j < 4; j++) bb[j] = KsT[e*65 + tx*4 + j];
            #pragma unroll
            for (int i = 0; i < 4; i++)
                #pragma unroll
                for (int j = 0; j < 4; j++) acc[i][j] += a[i]*bb[j];
        }
        #pragma unroll
        for (int i = 0; i < 4; i++)
            #pragma unroll
            for (int j = 0; j < 4; j++)
                sc[(ty*4 + i)*65 + tx*4 + j] = acc[i][j]*scale;
        __syncthreads();

        // online softmax: 4 lanes per row (lanes row*4+j are warp-aligned groups)
        {
            int row = tid >> 2, jj = tid & 3;
            float mold = m_s[row];
            float pmax = -1e30f;
            #pragma unroll
            for (int c = 0; c < 16; c++)
                pmax = fmaxf(pmax, sc[row*65 + jj*16 + c]);
            pmax = fmaxf(pmax, __shfl_xor_sync(0xffffffffu, pmax, 1));
            pmax = fmaxf(pmax, __shfl_xor_sync(0xffffffffu, pmax, 2));
            float mnew = fmaxf(mold, pmax);
            float psum = 0.f;
            #pragma unroll
            for (int c = 0; c < 16; c++) {
                float p = __expf(sc[row*65 + jj*16 + c] - mnew);
                sc[row*65 + jj*16 + c] = p;
                psum += p;
            }
            psum += __shfl_xor_sync(0xffffffffu, psum, 1);
            psum += __shfl_xor_sync(0xffffffffu, psum, 2);
            if (jj == 0) {
                float al = __expf(mold - mnew);
                al_s[row] = al;
                l_s[row]  = l_s[row]*al + psum;
                m_s[row]  = mnew;
            }
        }
        __syncthreads();

        // O = O*alpha + P @ V
        float al[4];
        #pragma unroll
        for (int i = 0; i < 4; i++) al[i] = al_s[ty*4 + i];
        #pragma unroll
        for (int i = 0; i < 4; i++)
            #pragma unroll
            for (int j = 0; j < 4; j++) o[i][j] *= al[i];
        #pragma unroll
        for (int kk = 0; kk < 64; kk++) {
            float p[4], vv[4];
            #pragma unroll
            for (int i = 0; i < 4; i++) p[i]  = sc[(ty*4 + i)*65 + kk];
            #pragma unroll
            for (int j = 0; j < 4; j++) vv[j] = Vs[kk*65 + tx*4 + j];
            #pragma unroll
            for (int i = 0; i < 4; i++)
                #pragma unroll
                for (int j = 0; j < 4; j++) o[i][j] += p[i]*vv[j];
        }
    }
    __syncthreads();

    #pragma unroll
    for (int i = 0; i < 4; i++) {
        int s = q0 + ty*4 + i;
        float inv = 1.0f / l_s[ty*4 + i];
        #pragma unroll
        for (int j = 0; j < 4; j++)
            g_attn[((b*Ss + s)*Hh + h)*Ee + tx*4 + j] = o[i][j]*inv;
    }
}

// ---------------------------------------------------------------------------
// Kernel 3: output projection. out = attn @ Wp + bp.  grid(BS/64, D/64).
// ---------------------------------------------------------------------------
__global__ __launch_bounds__(256) void proj_kernel(
    const float* __restrict__ Wp, const float* __restrict__ bp,
    float* __restrict__ out)
{
    __shared__ float as[64][33];
    __shared__ float bsm[32][64];

    const int m0 = blockIdx.x * 64;
    const int n0 = blockIdx.y * 64;
    const int tid = threadIdx.x;
    const int tx = tid & 15, ty = tid >> 4;

    float acc[4][4] = {};

    for (int k0 = 0; k0 < Dd; k0 += 32) {
        #pragma unroll
        for (int i = 0; i < 8; i++) {
            int li = tid + i*256;
            int r = li >> 5, c = li & 31;
            as[r][c] = g_attn[(m0 + r)*Dd + k0 + c];
        }
        #pragma unroll
        for (int i = 0; i < 8; i++) {
            int li = tid + i*256;
            int r = li >> 6, c = li & 63;
            bsm[r][c] = Wp[(k0 + r)*Dd + n0 + c];
        }
        __syncthreads();
        #pragma unroll
        for (int kk = 0; kk < 32; kk++) {
            float a[4], bb[4];
            #pragma unroll
            for (int i = 0; i < 4; i++) a[i]  = as[ty*4 + i][kk];
            #pragma unroll
            for (int j = 0; j < 4; j++) bb[j] = bsm[kk][tx*4 + j];
            #pragma unroll
            for (int i = 0; i < 4; i++)
                #pragma unroll
                for (int j = 0; j < 4; j++) acc[i][j] += a[i]*bb[j];
        }
        __syncthreads();
    }

    #pragma unroll
    for (int i = 0; i < 4; i++)
        #pragma unroll
        for (int j = 0; j < 4; j++)
            out[(m0 + ty*4 + i)*Dd + n0 + tx*4 + j] = acc[i][j] + bp[n0 + tx*4 + j];
}

// ---------------------------------------------------------------------------
extern "C" void kernel_launch(void* const* d_in, const int* in_sizes, int n_in,
                              void* d_out, int out_size)
{
    const float* x  = (const float*)d_in[0];
    const float* Wq = (const float*)d_in[1];
    const float* bq = (const float*)d_in[2];
    const float* Wk = (const float*)d_in[3];
    const float* bk = (const float*)d_in[4];
    const float* Wv = (const float*)d_in[5];
    const float* bv = (const float*)d_in[6];
    const float* Wp = (const float*)d_in[7];
    const float* bp = (const float*)d_in[8];
    float* out = (float*)d_out;

    const size_t attn_smem = (size_t)(4*64*65 + 3*64) * sizeof(float);  // ~67 KB
    cudaFuncSetAttribute(attn_kernel,
                         cudaFuncAttributeMaxDynamicSharedMemorySize,
                         (int)attn_smem);

    qkv_kernel<<<dim3(BS/64, Hh), 256>>>(x, Wq, bq, Wk, bk, Wv, bv);
    attn_kernel<<<dim3(Ss/64, Hh, Bb), 256, attn_smem>>>();
    proj_kernel<<<dim3(BS/64, Dd/64), 256>>>(Wp, bp, out);
}

// round 4
// speedup vs baseline: 2.1210x; 2.1210x over previous
#include <cuda_runtime.h>
#include <cuda_bf16.h>
#include <math.h>
#include <stdint.h>

#define Bb 4
#define Ss 2048
#define Dd 768
#define Hh 12
#define Ee 64
#define BS (Bb*Ss)
#define NQKV (3*Hh*Ee)   /* 2304 */

// ---------------------------------------------------------------------------
// Scratch (device globals: allocation-free rule)
// ---------------------------------------------------------------------------
__device__ __align__(16) float g_q[Bb*Hh*Ss*Ee];     // [B,H,S,E]
__device__ __align__(16) float g_k[Bb*Hh*Ss*Ee];
__device__ __align__(16) float g_v[Bb*Hh*Ss*Ee];
__device__ __align__(16) float g_attn[Bb*Ss*Hh*Ee];  // [B,S,H*E]

__device__ __align__(16) __nv_bfloat16 g_xh[BS*Dd],   g_xl[BS*Dd];   // x split [M][K]
__device__ __align__(16) __nv_bfloat16 g_wh[NQKV*Dd], g_wl[NQKV*Dd]; // qkv W [N][K]
__device__ __align__(16) __nv_bfloat16 g_ah[BS*Dd],   g_al[BS*Dd];   // attn split [M][K]
__device__ __align__(16) __nv_bfloat16 g_ph[Dd*Dd],   g_pl[Dd*Dd];   // Wp [N][K]

// ---------------------------------------------------------------------------
// PTX helpers (compute_103-safe: mma.sync / ldmatrix / cp.async only)
// ---------------------------------------------------------------------------
__device__ __forceinline__ uint32_t smem_u32(const void* p) {
    uint32_t a;
    asm("{ .reg .u64 t; cvta.to.shared.u64 t, %1; cvt.u32.u64 %0, t; }"
        : "=r"(a) : "l"(p));
    return a;
}
__device__ __forceinline__ void ldsm4(uint32_t r[4], uint32_t addr) {
    asm volatile("ldmatrix.sync.aligned.m8n8.x4.shared.b16 {%0,%1,%2,%3}, [%4];"
        : "=r"(r[0]), "=r"(r[1]), "=r"(r[2]), "=r"(r[3]) : "r"(addr));
}
__device__ __forceinline__ void ldsm4t(uint32_t r[4], uint32_t addr) {
    asm volatile("ldmatrix.sync.aligned.m8n8.x4.trans.shared.b16 {%0,%1,%2,%3}, [%4];"
        : "=r"(r[0]), "=r"(r[1]), "=r"(r[2]), "=r"(r[3]) : "r"(addr));
}
__device__ __forceinline__ void mma16816(float d[4], const uint32_t a[4],
                                         uint32_t b0, uint32_t b1) {
    asm volatile(
        "mma.sync.aligned.m16n8k16.row.col.f32.bf16.bf16.f32 "
        "{%0,%1,%2,%3}, {%4,%5,%6,%7}, {%8,%9}, {%0,%1,%2,%3};"
        : "+f"(d[0]), "+f"(d[1]), "+f"(d[2]), "+f"(d[3])
        : "r"(a[0]), "r"(a[1]), "r"(a[2]), "r"(a[3]), "r"(b0), "r"(b1));
}
#define CP16(sa, ga) asm volatile("cp.async.cg.shared.global [%0], [%1], 16;" :: "r"(sa), "l"(ga))
#define CP_COMMIT()  asm volatile("cp.async.commit_group;" ::: "memory")
#define CP_WAIT1()   asm volatile("cp.async.wait_group 1;" ::: "memory")
#define CP_WAIT0()   asm volatile("cp.async.wait_group 0;" ::: "memory")

// ---------------------------------------------------------------------------
// Conversion kernels: fp32 -> bf16 hi/lo split
// ---------------------------------------------------------------------------
__global__ void cvt_x(const float* __restrict__ x) {
    for (int i = blockIdx.x*blockDim.x + threadIdx.x; i < BS*Dd; i += gridDim.x*blockDim.x) {
        float f = x[i];
        __nv_bfloat16 h = __float2bfloat16(f);
        g_xh[i] = h;
        g_xl[i] = __float2bfloat16(f - __bfloat162float(h));
    }
}
__global__ void cvt_wqkv(const float* __restrict__ Wq, const float* __restrict__ Wk,
                         const float* __restrict__ Wv) {
    for (int i = blockIdx.x*blockDim.x + threadIdx.x; i < NQKV*Dd; i += gridDim.x*blockDim.x) {
        int n = i / Dd, k = i - n * Dd;
        int which = n / (Hh*Ee);
        int rr = n - which * (Hh*Ee);
        int h = rr >> 6, e = rr & 63;
        const float* W = (which == 0) ? Wq : (which == 1) ? Wk : Wv;
        float f = W[(h*Dd + k)*Ee + e];
        __nv_bfloat16 hb = __float2bfloat16(f);
        g_wh[i] = hb;
        g_wl[i] = __float2bfloat16(f - __bfloat162float(hb));
    }
}
__global__ void cvt_attn() {
    for (int i = blockIdx.x*blockDim.x + threadIdx.x; i < BS*Dd; i += gridDim.x*blockDim.x) {
        float f = g_attn[i];
        __nv_bfloat16 h = __float2bfloat16(f);
        g_ah[i] = h;
        g_al[i] = __float2bfloat16(f - __bfloat162float(h));
    }
}
__global__ void cvt_wp(const float* __restrict__ Wp) {
    for (int i = blockIdx.x*blockDim.x + threadIdx.x; i < Dd*Dd; i += gridDim.x*blockDim.x) {
        int n = i / Dd, k = i - n * Dd;
        float f = Wp[k*Dd + n];
        __nv_bfloat16 h = __float2bfloat16(f);
        g_ph[i] = h;
        g_pl[i] = __float2bfloat16(f - __bfloat162float(h));
    }
}

// ---------------------------------------------------------------------------
// GEMM via mma.sync bf16x3.  C[M][N] = A[M][K] * B[N][K]^T (+bias epilogue).
// CTA 128x128, 8 warps (2m x 4n), warp tile 64x32, K-chunk 32, cp.async 2-stage.
// MODE 0: QKV proj (scatter into g_q/g_k/g_v + bias). MODE 1: out proj.
// ---------------------------------------------------------------------------
#define GST 40                        /* smem row stride in bf16 elems */
#define GT  (128*GST*2)               /* one tile: 10240 B */
#define GSTAGE (4*GT)                 /* Ah,Al,Bh,Bl per stage: 40960 B */
#define GEMM_SMEM (2*GSTAGE)          /* 81920 B */
#define NCHUNK (Dd/32)                /* 24 */

template<int MODE>
__global__ __launch_bounds__(256) void gemm_mma(
    const float* __restrict__ bq, const float* __restrict__ bk,
    const float* __restrict__ bv, float* __restrict__ outp)
{
    extern __shared__ char smem[];
    const uint32_t sbase = smem_u32(smem);

    const __nv_bfloat16* __restrict__ Ah = (MODE == 0) ? g_xh : g_ah;
    const __nv_bfloat16* __restrict__ Al = (MODE == 0) ? g_xl : g_al;
    const __nv_bfloat16* __restrict__ Bh = (MODE == 0) ? g_wh : g_ph;
    const __nv_bfloat16* __restrict__ Bl = (MODE == 0) ? g_wl : g_pl;

    const int m0 = blockIdx.x * 128;
    const int n0 = blockIdx.y * 128;
    const int tid  = threadIdx.x;
    const int wid  = tid >> 5, lane = tid & 31;
    const int wm = wid & 1, wn = wid >> 1;   // warp tile: rows wm*64, cols wn*32

    float acc[4][4][4] = {};                 // [mt][nf][4]

    // ---- stage loader (cp.async, 16B) ----
    auto issue = [&](int s) {
        const int buf = s & 1;
        const uint32_t sd = sbase + buf * GSTAGE;
        const int k0 = s * 32;
        #pragma unroll
        for (int it = 0; it < 2; it++) {
            int u = tid + it * 256;          // 0..511
            int r = u >> 2, c8 = (u & 3) * 8;
            uint32_t off = (uint32_t)(r * GST + c8) * 2;
            size_t ai = (size_t)(m0 + r) * Dd + k0 + c8;
            size_t bi = (size_t)(n0 + r) * Dd + k0 + c8;
            CP16(sd + 0*GT + off, Ah + ai);
            CP16(sd + 1*GT + off, Al + ai);
            CP16(sd + 2*GT + off, Bh + bi);
            CP16(sd + 3*GT + off, Bl + bi);
        }
    };

    issue(0); CP_COMMIT();

    for (int s = 0; s < NCHUNK; s++) {
        if (s + 1 < NCHUNK) { issue(s + 1); CP_COMMIT(); CP_WAIT1(); }
        else                { CP_WAIT0(); }
        __syncthreads();

        const uint32_t sd  = sbase + (s & 1) * GSTAGE;
        const uint32_t sAh = sd, sAl = sd + GT, sBh = sd + 2*GT, sBl = sd + 3*GT;

        #pragma unroll
        for (int kk = 0; kk < 2; kk++) {
            // A fragments (row l%16, col (l/16)*8)
            uint32_t ah[4][4], al[4][4];
            uint32_t a_off = (uint32_t)((wm*64 + (lane & 15)) * GST + kk*16 + (lane >> 4)*8) * 2;
            #pragma unroll
            for (int mt = 0; mt < 4; mt++) {
                ldsm4(ah[mt], sAh + a_off + mt*16*GST*2);
                ldsm4(al[mt], sAl + a_off + mt*16*GST*2);
            }
            // B fragments: A-style addressing; x4 covers 16 n's:
            // pairing (r0,r2)=nf even, (r1,r3)=nf odd
            uint32_t bh[4][2], bl[4][2];
            uint32_t b_off = (uint32_t)((wn*32 + (lane & 15)) * GST + kk*16 + (lane >> 4)*8) * 2;
            #pragma unroll
            for (int half = 0; half < 2; half++) {
                uint32_t t[4];
                ldsm4(t, sBh + b_off + half*16*GST*2);
                bh[half*2+0][0] = t[0]; bh[half*2+0][1] = t[2];
                bh[half*2+1][0] = t[1]; bh[half*2+1][1] = t[3];
                ldsm4(t, sBl + b_off + half*16*GST*2);
                bl[half*2+0][0] = t[0]; bl[half*2+0][1] = t[2];
                bl[half*2+1][0] = t[1]; bl[half*2+1][1] = t[3];
            }
            #pragma unroll
            for (int mt = 0; mt < 4; mt++)
                #pragma unroll
                for (int nf = 0; nf < 4; nf++) {
                    mma16816(acc[mt][nf], ah[mt], bh[nf][0], bh[nf][1]);
                    mma16816(acc[mt][nf], ah[mt], bl[nf][0], bl[nf][1]);
                    mma16816(acc[mt][nf], al[mt], bh[nf][0], bh[nf][1]);
                }
        }
        __syncthreads();
    }

    // ---- epilogue ----
    #pragma unroll
    for (int mt = 0; mt < 4; mt++) {
        const int m = m0 + wm*64 + mt*16 + (lane >> 2);
        #pragma unroll
        for (int nf = 0; nf < 4; nf++) {
            if (MODE == 0) {
                int ng = n0 + wn*32 + nf*8;
                int which = ng / (Hh*Ee);
                int rr = ng - which * (Hh*Ee);
                int h = rr >> 6;
                int e0 = (rr & 63) + (lane & 3)*2;
                float* dst = (which == 0) ? g_q : (which == 1) ? g_k : g_v;
                const float* bsrc = (which == 0) ? bq : (which == 1) ? bk : bv;
                float b0f = bsrc[h*Ee + e0], b1f = bsrc[h*Ee + e0 + 1];
                int b = m >> 11, sI = m & 2047;
                size_t base = (((size_t)(b*Hh + h)) * Ss + sI) * Ee + e0;
                float2 v0 = { acc[mt][nf][0] + b0f, acc[mt][nf][1] + b1f };
                float2 v1 = { acc[mt][nf][2] + b0f, acc[mt][nf][3] + b1f };
                *(float2*)(dst + base)          = v0;
                *(float2*)(dst + base + 8*Ee)   = v1;   // row m+8 (same b,h)
            } else {
                int nn = n0 + wn*32 + nf*8 + (lane & 3)*2;
                float b0f = bq[nn], b1f = bq[nn + 1];   // bq carries bp
                float2 v0 = { acc[mt][nf][0] + b0f, acc[mt][nf][1] + b1f };
                float2 v1 = { acc[mt][nf][2] + b0f, acc[mt][nf][3] + b1f };
                *(float2*)(outp + (size_t)m*Dd + nn)       = v0;
                *(float2*)(outp + (size_t)(m+8)*Dd + nn)   = v1;
            }
        }
    }
}

// ---------------------------------------------------------------------------
// Flash attention via mma.sync bf16x3. CTA: 64 q-rows, 256 threads (8 warps,
// 4m x 2n: warp tile 16 q x 32 key/e). Scalar softmax (known-correct).
// K smem reused as split-P after softmax.
// ---------------------------------------------------------------------------
#define AST 72                          /* bf16 row stride (64+8) */
#define ATB (64*AST*2)                  /* 9216 B per bf16 tile */
// offsets (bytes): Qh 0, Ql, Kh, Kl, Vh, Vl, sc(fp32 64x65), m/l/al
#define OFF_QH 0
#define OFF_QL (OFF_QH + ATB)
#define OFF_KH (OFF_QL + ATB)
#define OFF_KL (OFF_KH + ATB)
#define OFF_VH (OFF_KL + ATB)
#define OFF_VL (OFF_VH + ATB)
#define OFF_SC (OFF_VL + ATB)
#define OFF_M  (OFF_SC + 64*65*4)
#define OFF_L  (OFF_M + 256)
#define OFF_AL (OFF_L + 256)
#define ATTN_SMEM (OFF_AL + 256)

__global__ __launch_bounds__(256) void attn_mma()
{
    extern __shared__ char smem[];
    const uint32_t sbase = smem_u32(smem);
    __nv_bfloat16* Qhs = (__nv_bfloat16*)(smem + OFF_QH);
    __nv_bfloat16* Qls = (__nv_bfloat16*)(smem + OFF_QL);
    __nv_bfloat16* Khs = (__nv_bfloat16*)(smem + OFF_KH);
    __nv_bfloat16* Kls = (__nv_bfloat16*)(smem + OFF_KL);
    __nv_bfloat16* Vhs = (__nv_bfloat16*)(smem + OFF_VH);
    __nv_bfloat16* Vls = (__nv_bfloat16*)(smem + OFF_VL);
    float* sc   = (float*)(smem + OFF_SC);
    float* m_s  = (float*)(smem + OFF_M);
    float* l_s  = (float*)(smem + OFF_L);
    float* al_s = (float*)(smem + OFF_AL);

    const int q0 = blockIdx.x * 64;
    const int h  = blockIdx.y;
    const int b  = blockIdx.z;
    const int tid = threadIdx.x;
    const int wid = tid >> 5, lane = tid & 31;
    const int wm = wid & 3, wn = wid >> 2;
    const int bh = b*Hh + h;
    const float* __restrict__ qp = g_q + (size_t)bh*Ss*Ee;
    const float* __restrict__ kp = g_k + (size_t)bh*Ss*Ee;
    const float* __restrict__ vp = g_v + (size_t)bh*Ss*Ee;

    // ---- load Q (split) + init stats ----
    #pragma unroll
    for (int it = 0; it < 4; it++) {
        int u = tid + it*256;
        int r = u >> 4, c4 = (u & 15)*4;
        float4 q4 = *(const float4*)(qp + (q0 + r)*Ee + c4);
        float f[4] = { q4.x, q4.y, q4.z, q4.w };
        #pragma unroll
        for (int j = 0; j < 4; j++) {
            __nv_bfloat16 hi = __float2bfloat16(f[j]);
            Qhs[r*AST + c4 + j] = hi;
            Qls[r*AST + c4 + j] = __float2bfloat16(f[j] - __bfloat162float(hi));
        }
    }
    if (tid < 64) { m_s[tid] = -1e30f; l_s[tid] = 0.f; }
    __syncthreads();

    // ---- preload Q fragments for all 4 k16 steps ----
    uint32_t qh[4][4], ql[4][4];
    {
        uint32_t base = (uint32_t)((wm*16 + (lane & 15)) * AST + (lane >> 4)*8) * 2;
        #pragma unroll
        for (int kk = 0; kk < 4; kk++) {
            ldsm4(qh[kk], sbase + OFF_QH + base + kk*32);  // kk*16 elems = 32 B
            ldsm4(ql[kk], sbase + OFF_QL + base + kk*32);
        }
    }

    float o[4][4] = {};
    const float scale = 0.125f;

    for (int k0 = 0; k0 < Ss; k0 += 64) {
        __syncthreads();   // prev PV done before overwriting K/V smem
        // ---- load K,V tile (split) ----
        #pragma unroll
        for (int it = 0; it < 4; it++) {
            int u = tid + it*256;
            int r = u >> 4, c4 = (u & 15)*4;
            float4 k4 = *(const float4*)(kp + (k0 + r)*Ee + c4);
            float4 v4 = *(const float4*)(vp + (k0 + r)*Ee + c4);
            float kf[4] = { k4.x, k4.y, k4.z, k4.w };
            float vf[4] = { v4.x, v4.y, v4.z, v4.w };
            #pragma unroll
            for (int j = 0; j < 4; j++) {
                __nv_bfloat16 khi = __float2bfloat16(kf[j]);
                Khs[r*AST + c4 + j] = khi;
                Kls[r*AST + c4 + j] = __float2bfloat16(kf[j] - __bfloat162float(khi));
                __nv_bfloat16 vhi = __float2bfloat16(vf[j]);
                Vhs[r*AST + c4 + j] = vhi;
                Vls[r*AST + c4 + j] = __float2bfloat16(vf[j] - __bfloat162float(vhi));
            }
        }
        __syncthreads();

        // ---- scores: S = Q K^T (bf16x3), warp tile 16 x 32 ----
        {
            float sacc[4][4] = {};
            uint32_t b_base = (uint32_t)((wn*32 + (lane & 15)) * AST + (lane >> 4)*8) * 2;
            #pragma unroll
            for (int kk = 0; kk < 4; kk++) {
                uint32_t kh[4][2], kl[4][2];
                #pragma unroll
                for (int half = 0; half < 2; half++) {
                    uint32_t t[4];
                    ldsm4(t, sbase + OFF_KH + b_base + half*16*AST*2 + kk*32);
                    kh[half*2+0][0] = t[0]; kh[half*2+0][1] = t[2];
                    kh[half*2+1][0] = t[1]; kh[half*2+1][1] = t[3];
                    ldsm4(t, sbase + OFF_KL + b_base + half*16*AST*2 + kk*32);
                    kl[half*2+0][0] = t[0]; kl[half*2+0][1] = t[2];
                    kl[half*2+1][0] = t[1]; kl[half*2+1][1] = t[3];
                }
                #pragma unroll
                for (int nf = 0; nf < 4; nf++) {
                    mma16816(sacc[nf], qh[kk], kh[nf][0], kh[nf][1]);
                    mma16816(sacc[nf], qh[kk], kl[nf][0], kl[nf][1]);
                    mma16816(sacc[nf], ql[kk], kh[nf][0], kh[nf][1]);
                }
            }
            const int row = wm*16 + (lane >> 2);
            #pragma unroll
            for (int nf = 0; nf < 4; nf++) {
                int col = wn*32 + nf*8 + (lane & 3)*2;
                sc[row*65 + col]       = sacc[nf][0]*scale;
                sc[row*65 + col + 1]   = sacc[nf][1]*scale;
                sc[(row+8)*65 + col]   = sacc[nf][2]*scale;
                sc[(row+8)*65 + col+1] = sacc[nf][3]*scale;
            }
        }
        __syncthreads();

        // ---- scalar online softmax; write split P into Khs/Kls ----
        {
            int row = tid >> 2, jj = tid & 3;
            float mold = m_s[row];
            float pmax = -1e30f;
            #pragma unroll
            for (int c = 0; c < 16; c++)
                pmax = fmaxf(pmax, sc[row*65 + jj*16 + c]);
            pmax = fmaxf(pmax, __shfl_xor_sync(0xffffffffu, pmax, 1));
            pmax = fmaxf(pmax, __shfl_xor_sync(0xffffffffu, pmax, 2));
            float mnew = fmaxf(mold, pmax);
            float psum = 0.f;
            #pragma unroll
            for (int c = 0; c < 16; c++) {
                int idx = jj*16 + c;
                float p = __expf(sc[row*65 + idx] - mnew);
                psum += p;
                __nv_bfloat16 ph = __float2bfloat16(p);
                Khs[row*AST + idx] = ph;
                Kls[row*AST + idx] = __float2bfloat16(p - __bfloat162float(ph));
            }
            psum += __shfl_xor_sync(0xffffffffu, psum, 1);
            psum += __shfl_xor_sync(0xffffffffu, psum, 2);
            if (jj == 0) {
                float al = __expf(mold - mnew);
                al_s[row] = al;
                l_s[row]  = l_s[row]*al + psum;
                m_s[row]  = mnew;
            }
        }
        __syncthreads();

        // ---- rescale O, then O += P V (bf16x3) ----
        {
            const int r0 = wm*16 + (lane >> 2);
            float al0 = al_s[r0], al1 = al_s[r0 + 8];
            #pragma unroll
            for (int nf = 0; nf < 4; nf++) {
                o[nf][0] *= al0; o[nf][1] *= al0;
                o[nf][2] *= al1; o[nf][3] *= al1;
            }
            uint32_t a_base = (uint32_t)((wm*16 + (lane & 15)) * AST + (lane >> 4)*8) * 2;
            #pragma unroll
            for (int kk = 0; kk < 4; kk++) {
                uint32_t ph[4], pl[4];
                ldsm4(ph, sbase + OFF_KH + a_base + kk*32);
                ldsm4(pl, sbase + OFF_KL + a_base + kk*32);
                // V fragments: trans ldmatrix; x4 covers e16: pairing (r0,r1),(r2,r3)
                uint32_t v_base = (uint32_t)((kk*16 + (lane & 15)) * AST
                                             + wn*32 + (lane >> 4)*8) * 2;
                uint32_t vh[4][2], vl[4][2];
                #pragma unroll
                for (int half = 0; half < 2; half++) {
                    uint32_t t[4];
                    ldsm4t(t, sbase + OFF_VH + v_base + half*32);  // e +16 = 32 B
                    vh[half*2+0][0] = t[0]; vh[half*2+0][1] = t[1];
                    vh[half*2+1][0] = t[2]; vh[half*2+1][1] = t[3];
                    ldsm4t(t, sbase + OFF_VL + v_base + half*32);
                    vl[half*2+0][0] = t[0]; vl[half*2+0][1] = t[1];
                    vl[half*2+1][0] = t[2]; vl[half*2+1][1] = t[3];
                }
                #pragma unroll
                for (int nf = 0; nf < 4; nf++) {
                    mma16816(o[nf], ph, vh[nf][0], vh[nf][1]);
                    mma16816(o[nf], ph, vl[nf][0], vl[nf][1]);
                    mma16816(o[nf], pl, vh[nf][0], vh[nf][1]);
                }
            }
        }
    }
    __syncthreads();

    // ---- normalize + store ----
    {
        const int r0 = wm*16 + (lane >> 2);
        float inv0 = 1.0f / l_s[r0], inv1 = 1.0f / l_s[r0 + 8];
        #pragma unroll
        for (int nf = 0; nf < 4; nf++) {
            int e = wn*32 + nf*8 + (lane & 3)*2;
            size_t b0 = (((size_t)(b*Ss + q0 + r0))*Hh + h)*Ee + e;
            size_t b1 = (((size_t)(b*Ss + q0 + r0 + 8))*Hh + h)*Ee + e;
            float2 v0 = { o[nf][0]*inv0, o[nf][1]*inv0 };
            float2 v1 = { o[nf][2]*inv1, o[nf][3]*inv1 };
            *(float2*)(g_attn + b0) = v0;
            *(float2*)(g_attn + b1) = v1;
        }
    }
}

// ---------------------------------------------------------------------------
extern "C" void kernel_launch(void* const* d_in, const int* in_sizes, int n_in,
                              void* d_out, int out_size)
{
    const float* x  = (const float*)d_in[0];
    const float* Wq = (const float*)d_in[1];
    const float* bq = (const float*)d_in[2];
    const float* Wk = (const float*)d_in[3];
    const float* bk = (const float*)d_in[4];
    const float* Wv = (const float*)d_in[5];
    const float* bv = (const float*)d_in[6];
    const float* Wp = (const float*)d_in[7];
    const float* bp = (const float*)d_in[8];
    float* out = (float*)d_out;

    cudaFuncSetAttribute(gemm_mma<0>, cudaFuncAttributeMaxDynamicSharedMemorySize, GEMM_SMEM);
    cudaFuncSetAttribute(gemm_mma<1>, cudaFuncAttributeMaxDynamicSharedMemorySize, GEMM_SMEM);
    cudaFuncSetAttribute(attn_mma,    cudaFuncAttributeMaxDynamicSharedMemorySize, ATTN_SMEM);

    cvt_x<<<2048, 256>>>(x);
    cvt_wqkv<<<1024, 256>>>(Wq, Wk, Wv);
    gemm_mma<0><<<dim3(BS/128, NQKV/128), 256, GEMM_SMEM>>>(bq, bk, bv, nullptr);
    attn_mma<<<dim3(Ss/64, Hh, Bb), 256, ATTN_SMEM>>>();
    cvt_attn<<<2048, 256>>>();
    cvt_wp<<<512, 256>>>(Wp);
    gemm_mma<1><<<dim3(BS/128, Dd/128), 256, GEMM_SMEM>>>(bp, nullptr, nullptr, out);
}

// round 5
// speedup vs baseline: 2.8350x; 1.3367x over previous
#include <cuda_runtime.h>
#include <cuda_bf16.h>
#include <math.h>
#include <stdint.h>

#define Bb 4
#define Ss 2048
#define Dd 768
#define Hh 12
#define Ee 64
#define BS (Bb*Ss)
#define NQKV (3*Hh*Ee)   /* 2304 */

// ---------------------------------------------------------------------------
// Scratch (device globals: allocation-free rule)
// ---------------------------------------------------------------------------
__device__ __align__(16) __nv_bfloat16 g_xh[BS*Dd],   g_xl[BS*Dd];   // x split [M][K]
__device__ __align__(16) __nv_bfloat16 g_wh[NQKV*Dd], g_wl[NQKV*Dd]; // qkv W [N][K]
__device__ __align__(16) __nv_bfloat16 g_ah[BS*Dd],   g_al[BS*Dd];   // attn out split [M][K]
__device__ __align__(16) __nv_bfloat16 g_ph[Dd*Dd],   g_pl[Dd*Dd];   // Wp [N][K]
// q/k/v bf16 hi/lo, layout [B,H,S,E]
__device__ __align__(16) __nv_bfloat16 g_qh[Bb*Hh*Ss*Ee], g_ql[Bb*Hh*Ss*Ee];
__device__ __align__(16) __nv_bfloat16 g_kh[Bb*Hh*Ss*Ee], g_kl[Bb*Hh*Ss*Ee];
__device__ __align__(16) __nv_bfloat16 g_vh[Bb*Hh*Ss*Ee], g_vl[Bb*Hh*Ss*Ee];

// ---------------------------------------------------------------------------
// PTX helpers (compute_103-safe: mma.sync / ldmatrix / cp.async only)
// ---------------------------------------------------------------------------
__device__ __forceinline__ uint32_t smem_u32(const void* p) {
    uint32_t a;
    asm("{ .reg .u64 t; cvta.to.shared.u64 t, %1; cvt.u32.u64 %0, t; }"
        : "=r"(a) : "l"(p));
    return a;
}
__device__ __forceinline__ void ldsm4(uint32_t r[4], uint32_t addr) {
    asm volatile("ldmatrix.sync.aligned.m8n8.x4.shared.b16 {%0,%1,%2,%3}, [%4];"
        : "=r"(r[0]), "=r"(r[1]), "=r"(r[2]), "=r"(r[3]) : "r"(addr));
}
__device__ __forceinline__ void ldsm4t(uint32_t r[4], uint32_t addr) {
    asm volatile("ldmatrix.sync.aligned.m8n8.x4.trans.shared.b16 {%0,%1,%2,%3}, [%4];"
        : "=r"(r[0]), "=r"(r[1]), "=r"(r[2]), "=r"(r[3]) : "r"(addr));
}
__device__ __forceinline__ void mma16816(float d[4], const uint32_t a[4],
                                         uint32_t b0, uint32_t b1) {
    asm volatile(
        "mma.sync.aligned.m16n8k16.row.col.f32.bf16.bf16.f32 "
        "{%0,%1,%2,%3}, {%4,%5,%6,%7}, {%8,%9}, {%0,%1,%2,%3};"
        : "+f"(d[0]), "+f"(d[1]), "+f"(d[2]), "+f"(d[3])
        : "r"(a[0]), "r"(a[1]), "r"(a[2]), "r"(a[3]), "r"(b0), "r"(b1));
}
__device__ __forceinline__ float ex2f(float x) {
    float y; asm("ex2.approx.f32 %0, %1;" : "=f"(y) : "f"(x)); return y;
}
// split two floats into packed bf16 hi / bf16 lo words
__device__ __forceinline__ void split2(float a, float b, uint32_t& hi, uint32_t& lo) {
    __nv_bfloat16 ha = __float2bfloat16(a), hb = __float2bfloat16(b);
    __nv_bfloat16 la = __float2bfloat16(a - __bfloat162float(ha));
    __nv_bfloat16 lb = __float2bfloat16(b - __bfloat162float(hb));
    __nv_bfloat162 hv; hv.x = ha; hv.y = hb;
    __nv_bfloat162 lv; lv.x = la; lv.y = lb;
    hi = *(uint32_t*)&hv; lo = *(uint32_t*)&lv;
}
#define CP16(sa, ga) asm volatile("cp.async.cg.shared.global [%0], [%1], 16;" :: "r"(sa), "l"(ga))
#define CP_COMMIT()  asm volatile("cp.async.commit_group;" ::: "memory")
#define CP_WAIT1()   asm volatile("cp.async.wait_group 1;" ::: "memory")
#define CP_WAIT0()   asm volatile("cp.async.wait_group 0;" ::: "memory")

// ---------------------------------------------------------------------------
// Conversion kernels: fp32 -> bf16 hi/lo split
// ---------------------------------------------------------------------------
__global__ void cvt_x(const float* __restrict__ x) {
    for (int i = blockIdx.x*blockDim.x + threadIdx.x; i < BS*Dd; i += gridDim.x*blockDim.x) {
        float f = x[i];
        __nv_bfloat16 h = __float2bfloat16(f);
        g_xh[i] = h;
        g_xl[i] = __float2bfloat16(f - __bfloat162float(h));
    }
}
__global__ void cvt_wqkv(const float* __restrict__ Wq, const float* __restrict__ Wk,
                         const float* __restrict__ Wv) {
    for (int i = blockIdx.x*blockDim.x + threadIdx.x; i < NQKV*Dd; i += gridDim.x*blockDim.x) {
        int n = i / Dd, k = i - n * Dd;
        int which = n / (Hh*Ee);
        int rr = n - which * (Hh*Ee);
        int h = rr >> 6, e = rr & 63;
        const float* W = (which == 0) ? Wq : (which == 1) ? Wk : Wv;
        float f = W[(h*Dd + k)*Ee + e];
        __nv_bfloat16 hb = __float2bfloat16(f);
        g_wh[i] = hb;
        g_wl[i] = __float2bfloat16(f - __bfloat162float(hb));
    }
}
__global__ void cvt_wp(const float* __restrict__ Wp) {
    for (int i = blockIdx.x*blockDim.x + threadIdx.x; i < Dd*Dd; i += gridDim.x*blockDim.x) {
        int n = i / Dd, k = i - n * Dd;
        float f = Wp[k*Dd + n];
        __nv_bfloat16 h = __float2bfloat16(f);
        g_ph[i] = h;
        g_pl[i] = __float2bfloat16(f - __bfloat162float(h));
    }
}

// ---------------------------------------------------------------------------
// GEMM via mma.sync bf16x3.  C[M][N] = A[M][K] * B[N][K]^T (+bias epilogue).
// CTA 128x128, 8 warps (2m x 4n), warp tile 64x32, K-chunk 32, cp.async 2-stage.
// MODE 0: QKV proj -> writes bf16 hi/lo q/k/v arrays (+bias).
// MODE 1: out proj -> fp32 out (+bp, passed via bq).
// ---------------------------------------------------------------------------
#define GST 40                        /* smem row stride in bf16 elems */
#define GT  (128*GST*2)               /* one tile: 10240 B */
#define GSTAGE (4*GT)                 /* Ah,Al,Bh,Bl per stage: 40960 B */
#define GEMM_SMEM (2*GSTAGE)          /* 81920 B */
#define NCHUNK (Dd/32)                /* 24 */

template<int MODE>
__global__ __launch_bounds__(256) void gemm_mma(
    const float* __restrict__ bq, const float* __restrict__ bk,
    const float* __restrict__ bv, float* __restrict__ outp)
{
    extern __shared__ char smem[];
    const uint32_t sbase = smem_u32(smem);

    const __nv_bfloat16* __restrict__ Ah = (MODE == 0) ? g_xh : g_ah;
    const __nv_bfloat16* __restrict__ Al = (MODE == 0) ? g_xl : g_al;
    const __nv_bfloat16* __restrict__ Bh = (MODE == 0) ? g_wh : g_ph;
    const __nv_bfloat16* __restrict__ Bl = (MODE == 0) ? g_wl : g_pl;

    const int m0 = blockIdx.x * 128;
    const int n0 = blockIdx.y * 128;
    const int tid  = threadIdx.x;
    const int wid  = tid >> 5, lane = tid & 31;
    const int wm = wid & 1, wn = wid >> 1;

    float acc[4][4][4] = {};

    auto issue = [&](int s) {
        const int buf = s & 1;
        const uint32_t sd = sbase + buf * GSTAGE;
        const int k0 = s * 32;
        #pragma unroll
        for (int it = 0; it < 2; it++) {
            int u = tid + it * 256;
            int r = u >> 2, c8 = (u & 3) * 8;
            uint32_t off = (uint32_t)(r * GST + c8) * 2;
            size_t ai = (size_t)(m0 + r) * Dd + k0 + c8;
            size_t bi = (size_t)(n0 + r) * Dd + k0 + c8;
            CP16(sd + 0*GT + off, Ah + ai);
            CP16(sd + 1*GT + off, Al + ai);
            CP16(sd + 2*GT + off, Bh + bi);
            CP16(sd + 3*GT + off, Bl + bi);
        }
    };

    issue(0); CP_COMMIT();

    for (int s = 0; s < NCHUNK; s++) {
        if (s + 1 < NCHUNK) { issue(s + 1); CP_COMMIT(); CP_WAIT1(); }
        else                { CP_WAIT0(); }
        __syncthreads();

        const uint32_t sd  = sbase + (s & 1) * GSTAGE;
        const uint32_t sAh = sd, sAl = sd + GT, sBh = sd + 2*GT, sBl = sd + 3*GT;

        #pragma unroll
        for (int kk = 0; kk < 2; kk++) {
            uint32_t ah[4][4], al[4][4];
            uint32_t a_off = (uint32_t)((wm*64 + (lane & 15)) * GST + kk*16 + (lane >> 4)*8) * 2;
            #pragma unroll
            for (int mt = 0; mt < 4; mt++) {
                ldsm4(ah[mt], sAh + a_off + mt*16*GST*2);
                ldsm4(al[mt], sAl + a_off + mt*16*GST*2);
            }
            uint32_t bh[4][2], bl[4][2];
            uint32_t b_off = (uint32_t)((wn*32 + (lane & 15)) * GST + kk*16 + (lane >> 4)*8) * 2;
            #pragma unroll
            for (int half = 0; half < 2; half++) {
                uint32_t t[4];
                ldsm4(t, sBh + b_off + half*16*GST*2);
                bh[half*2+0][0] = t[0]; bh[half*2+0][1] = t[2];
                bh[half*2+1][0] = t[1]; bh[half*2+1][1] = t[3];
                ldsm4(t, sBl + b_off + half*16*GST*2);
                bl[half*2+0][0] = t[0]; bl[half*2+0][1] = t[2];
                bl[half*2+1][0] = t[1]; bl[half*2+1][1] = t[3];
            }
            #pragma unroll
            for (int mt = 0; mt < 4; mt++)
                #pragma unroll
                for (int nf = 0; nf < 4; nf++) {
                    mma16816(acc[mt][nf], ah[mt], bh[nf][0], bh[nf][1]);
                    mma16816(acc[mt][nf], ah[mt], bl[nf][0], bl[nf][1]);
                    mma16816(acc[mt][nf], al[mt], bh[nf][0], bh[nf][1]);
                }
        }
        __syncthreads();
    }

    // ---- epilogue ----
    #pragma unroll
    for (int mt = 0; mt < 4; mt++) {
        const int m = m0 + wm*64 + mt*16 + (lane >> 2);
        #pragma unroll
        for (int nf = 0; nf < 4; nf++) {
            if (MODE == 0) {
                int ng = n0 + wn*32 + nf*8;
                int which = ng / (Hh*Ee);
                int rr = ng - which * (Hh*Ee);
                int h = rr >> 6;
                int e0 = (rr & 63) + (lane & 3)*2;
                __nv_bfloat16* dh = (which == 0) ? g_qh : (which == 1) ? g_kh : g_vh;
                __nv_bfloat16* dl = (which == 0) ? g_ql : (which == 1) ? g_kl : g_vl;
                const float* bsrc = (which == 0) ? bq : (which == 1) ? bk : bv;
                float b0f = bsrc[h*Ee + e0], b1f = bsrc[h*Ee + e0 + 1];
                int b = m >> 11, sI = m & 2047;
                size_t base = (((size_t)(b*Hh + h)) * Ss + sI) * Ee + e0;
                uint32_t hw, lw;
                split2(acc[mt][nf][0] + b0f, acc[mt][nf][1] + b1f, hw, lw);
                *(uint32_t*)(dh + base) = hw;
                *(uint32_t*)(dl + base) = lw;
                split2(acc[mt][nf][2] + b0f, acc[mt][nf][3] + b1f, hw, lw);
                *(uint32_t*)(dh + base + 8*Ee) = hw;   // row m+8 (same b,h)
                *(uint32_t*)(dl + base + 8*Ee) = lw;
            } else {
                int nn = n0 + wn*32 + nf*8 + (lane & 3)*2;
                float b0f = bq[nn], b1f = bq[nn + 1];   // bq carries bp
                float2 v0 = { acc[mt][nf][0] + b0f, acc[mt][nf][1] + b1f };
                float2 v1 = { acc[mt][nf][2] + b0f, acc[mt][nf][3] + b1f };
                *(float2*)(outp + (size_t)m*Dd + nn)       = v0;
                *(float2*)(outp + (size_t)(m+8)*Dd + nn)   = v1;
            }
        }
    }
}

// ---------------------------------------------------------------------------
// Flash attention, register-resident softmax.
// CTA: 64 q-rows, 128 threads (4 warps x 16 q-rows x all 64 keys).
// K/V bf16 split streamed via double-buffered cp.async. P never leaves regs.
// ---------------------------------------------------------------------------
#define AST 72                 /* bf16 row stride (64+8) */
#define SUBB (64*AST*2)        /* one 64x64 bf16 subtile: 9216 B */
#define STG (4*SUBB)           /* stage: Kh,Kl,Vh,Vl = 36864 B */
#define ATTN_SMEM (2*STG)      /* 73728 B */

__global__ __launch_bounds__(128, 3) void attn_mma()
{
    extern __shared__ char smem[];
    const uint32_t sbase = smem_u32(smem);
    const int q0 = blockIdx.x * 64;
    const int h  = blockIdx.y;
    const int b  = blockIdx.z;
    const int tid = threadIdx.x;
    const int wid = tid >> 5, lane = tid & 31;
    const size_t gbase = (size_t)(b*Hh + h) * Ss * Ee;
    const __nv_bfloat16* __restrict__ qhp = g_qh + gbase;
    const __nv_bfloat16* __restrict__ qlp = g_ql + gbase;
    const __nv_bfloat16* __restrict__ khp = g_kh + gbase;
    const __nv_bfloat16* __restrict__ klp = g_kl + gbase;
    const __nv_bfloat16* __restrict__ vhp = g_vh + gbase;
    const __nv_bfloat16* __restrict__ vlp = g_vl + gbase;

    // ---- stage Q (hi/lo) into stage-1 region ----
    #pragma unroll
    for (int i = 0; i < 8; i++) {
        int arr = i >> 2;                 // 0 hi, 1 lo
        int rem = (i & 3)*128 + tid;      // 0..511
        int r = rem >> 3, c16 = rem & 7;
        uint32_t sa = sbase + STG + arr*SUBB + (uint32_t)r*(AST*2) + c16*16;
        const __nv_bfloat16* gp = (arr ? qlp : qhp) + (q0 + r)*Ee + c16*8;
        CP16(sa, gp);
    }
    CP_COMMIT();

    // ---- prefetch KV tile 0 into stage 0 ----
    #pragma unroll
    for (int i = 0; i < 16; i++) {
        int sub = i >> 2;                 // 0 Kh, 1 Kl, 2 Vh, 3 Vl
        int rem = (i & 3)*128 + tid;
        int r = rem >> 3, c16 = rem & 7;
        const __nv_bfloat16* gp =
            (sub == 0 ? khp : sub == 1 ? klp : sub == 2 ? vhp : vlp) + r*Ee + c16*8;
        CP16(sbase + sub*SUBB + (uint32_t)r*(AST*2) + c16*16, gp);
    }
    CP_COMMIT();

    CP_WAIT1();            // Q ready (KV0 may still be in flight)
    __syncthreads();

    // ---- Q fragments (all 4 k16 steps, hi+lo) ----
    uint32_t qh[4][4], ql[4][4];
    {
        uint32_t qoff = (uint32_t)(wid*16 + (lane & 15))*(AST*2) + (lane >> 4)*16;
        #pragma unroll
        for (int kk = 0; kk < 4; kk++) {
            ldsm4(qh[kk], sbase + STG + qoff + kk*32);
            ldsm4(ql[kk], sbase + STG + SUBB + qoff + kk*32);
        }
    }
    __syncthreads();       // Q region (stage 1) may now be overwritten by KV1

    float o[8][4] = {};
    float m0 = -1e30f, m1 = -1e30f, l0 = 0.f, l1 = 0.f;
    const float Cc = 0.18033688011112042f;   // 0.125 * log2(e)

    for (int s = 0; s < Ss/64; s++) {
        if (s + 1 < Ss/64) {
            const uint32_t stn = sbase + ((s+1) & 1)*STG;
            const int k0 = (s+1)*64;
            #pragma unroll
            for (int i = 0; i < 16; i++) {
                int sub = i >> 2;
                int rem = (i & 3)*128 + tid;
                int r = rem >> 3, c16 = rem & 7;
                const __nv_bfloat16* gp =
                    (sub == 0 ? khp : sub == 1 ? klp : sub == 2 ? vhp : vlp)
                    + (k0 + r)*Ee + c16*8;
                CP16(stn + sub*SUBB + (uint32_t)r*(AST*2) + c16*16, gp);
            }
            CP_COMMIT();
            CP_WAIT1();
        } else {
            CP_WAIT0();
        }
        __syncthreads();

        const uint32_t st = sbase + (s & 1)*STG;

        // ---- S = Q K^T (bf16x3), raw (scale folded into exp) ----
        float sacc[8][4];
        #pragma unroll
        for (int nf = 0; nf < 8; nf++) {
            sacc[nf][0] = 0.f; sacc[nf][1] = 0.f; sacc[nf][2] = 0.f; sacc[nf][3] = 0.f;
        }
        uint32_t kbase = (uint32_t)(lane & 15)*(AST*2) + (lane >> 4)*16;
        #pragma unroll
        for (int kk = 0; kk < 4; kk++) {
            #pragma unroll
            for (int g = 0; g < 4; g++) {
                uint32_t th[4], tl[4];
                uint32_t ad = st + kbase + (uint32_t)g*16*(AST*2) + kk*32;
                ldsm4(th, ad);            // K hi
                ldsm4(tl, ad + SUBB);     // K lo
                mma16816(sacc[2*g],   qh[kk], th[0], th[2]);
                mma16816(sacc[2*g+1], qh[kk], th[1], th[3]);
                mma16816(sacc[2*g],   qh[kk], tl[0], tl[2]);
                mma16816(sacc[2*g+1], qh[kk], tl[1], tl[3]);
                mma16816(sacc[2*g],   ql[kk], th[0], th[2]);
                mma16816(sacc[2*g+1], ql[kk], th[1], th[3]);
            }
        }

        // ---- online softmax, fully in registers (rows warp-local) ----
        float r0 = -1e30f, r1 = -1e30f;
        #pragma unroll
        for (int nf = 0; nf < 8; nf++) {
            r0 = fmaxf(r0, fmaxf(sacc[nf][0], sacc[nf][1]));
            r1 = fmaxf(r1, fmaxf(sacc[nf][2], sacc[nf][3]));
        }
        r0 = fmaxf(r0, __shfl_xor_sync(0xffffffffu, r0, 1));
        r0 = fmaxf(r0, __shfl_xor_sync(0xffffffffu, r0, 2));
        r1 = fmaxf(r1, __shfl_xor_sync(0xffffffffu, r1, 1));
        r1 = fmaxf(r1, __shfl_xor_sync(0xffffffffu, r1, 2));
        float mn0 = fmaxf(m0, r0), mn1 = fmaxf(m1, r1);
        float al0 = ex2f((m0 - mn0)*Cc), al1 = ex2f((m1 - mn1)*Cc);
        m0 = mn0; m1 = mn1;

        float p[8][4];
        float ps0 = 0.f, ps1 = 0.f;
        #pragma unroll
        for (int nf = 0; nf < 8; nf++) {
            p[nf][0] = ex2f((sacc[nf][0] - mn0)*Cc);
            p[nf][1] = ex2f((sacc[nf][1] - mn0)*Cc);
            p[nf][2] = ex2f((sacc[nf][2] - mn1)*Cc);
            p[nf][3] = ex2f((sacc[nf][3] - mn1)*Cc);
            ps0 += p[nf][0] + p[nf][1];
            ps1 += p[nf][2] + p[nf][3];
        }
        ps0 += __shfl_xor_sync(0xffffffffu, ps0, 1);
        ps0 += __shfl_xor_sync(0xffffffffu, ps0, 2);
        ps1 += __shfl_xor_sync(0xffffffffu, ps1, 1);
        ps1 += __shfl_xor_sync(0xffffffffu, ps1, 2);
        l0 = l0*al0 + ps0;
        l1 = l1*al1 + ps1;

        // ---- P fragments in registers (A-layout, hi/lo split) ----
        uint32_t pfh[4][4], pfl[4][4];
        #pragma unroll
        for (int kk = 0; kk < 4; kk++) {
            int n0f = 2*kk, n1f = 2*kk + 1;
            split2(p[n0f][0], p[n0f][1], pfh[kk][0], pfl[kk][0]);
            split2(p[n0f][2], p[n0f][3], pfh[kk][1], pfl[kk][1]);
            split2(p[n1f][0], p[n1f][1], pfh[kk][2], pfl[kk][2]);
            split2(p[n1f][2], p[n1f][3], pfh[kk][3], pfl[kk][3]);
        }

        // ---- rescale O, then O += P V (bf16x3) ----
        #pragma unroll
        for (int nf = 0; nf < 8; nf++) {
            o[nf][0] *= al0; o[nf][1] *= al0;
            o[nf][2] *= al1; o[nf][3] *= al1;
        }
        #pragma unroll
        for (int kk = 0; kk < 4; kk++) {
            uint32_t vb = st + 2*SUBB + (uint32_t)(kk*16 + (lane & 15))*(AST*2)
                          + (lane >> 4)*16;
            #pragma unroll
            for (int g = 0; g < 4; g++) {          // e16 groups
                uint32_t th[4], tl[4];
                ldsm4t(th, vb + g*32);             // V hi
                ldsm4t(tl, vb + SUBB + g*32);      // V lo
                mma16816(o[2*g],   pfh[kk], th[0], th[1]);
                mma16816(o[2*g+1], pfh[kk], th[2], th[3]);
                mma16816(o[2*g],   pfh[kk], tl[0], tl[1]);
                mma16816(o[2*g+1], pfh[kk], tl[2], tl[3]);
                mma16816(o[2*g],   pfl[kk], th[0], th[1]);
                mma16816(o[2*g+1], pfl[kk], th[2], th[3]);
            }
        }
        __syncthreads();   // stage fully consumed before next iter's issue
    }

    // ---- normalize + store bf16 split directly (feeds proj GEMM) ----
    {
        const int r0i = wid*16 + (lane >> 2);
        float inv0 = 1.0f / l0, inv1 = 1.0f / l1;
        #pragma unroll
        for (int nf = 0; nf < 8; nf++) {
            int e = nf*8 + (lane & 3)*2;
            size_t i0 = ((size_t)(b*Ss + q0 + r0i)*Hh + h)*Ee + e;
            size_t i1 = i0 + (size_t)8*Hh*Ee;
            uint32_t hw, lw;
            split2(o[nf][0]*inv0, o[nf][1]*inv0, hw, lw);
            *(uint32_t*)(g_ah + i0) = hw;
            *(uint32_t*)(g_al + i0) = lw;
            split2(o[nf][2]*inv1, o[nf][3]*inv1, hw, lw);
            *(uint32_t*)(g_ah + i1) = hw;
            *(uint32_t*)(g_al + i1) = lw;
        }
    }
}

// ---------------------------------------------------------------------------
extern "C" void kernel_launch(void* const* d_in, const int* in_sizes, int n_in,
                              void* d_out, int out_size)
{
    const float* x  = (const float*)d_in[0];
    const float* Wq = (const float*)d_in[1];
    const float* bq = (const float*)d_in[2];
    const float* Wk = (const float*)d_in[3];
    const float* bk = (const float*)d_in[4];
    const float* Wv = (const float*)d_in[5];
    const float* bv = (const float*)d_in[6];
    const float* Wp = (const float*)d_in[7];
    const float* bp = (const float*)d_in[8];
    float* out = (float*)d_out;

    cudaFuncSetAttribute(gemm_mma<0>, cudaFuncAttributeMaxDynamicSharedMemorySize, GEMM_SMEM);
    cudaFuncSetAttribute(gemm_mma<1>, cudaFuncAttributeMaxDynamicSharedMemorySize, GEMM_SMEM);
    cudaFuncSetAttribute(attn_mma,    cudaFuncAttributeMaxDynamicSharedMemorySize, ATTN_SMEM);

    cvt_x<<<2048, 256>>>(x);
    cvt_wqkv<<<1024, 256>>>(Wq, Wk, Wv);
    gemm_mma<0><<<dim3(BS/128, NQKV/128), 256, GEMM_SMEM>>>(bq, bk, bv, nullptr);
    attn_mma<<<dim3(Ss/64, Hh, Bb), 128, ATTN_SMEM>>>();
    cvt_wp<<<512, 256>>>(Wp);
    gemm_mma<1><<<dim3(BS/128, Dd/128), 256, GEMM_SMEM>>>(bp, nullptr, nullptr, out);
}

// round 7
// speedup vs baseline: 3.0458x; 1.0743x over previous
#include <cuda_runtime.h>
#include <cuda_bf16.h>
#include <math.h>
#include <stdint.h>

#define Bb 4
#define Ss 2048
#define Dd 768
#define Hh 12
#define Ee 64
#define BS (Bb*Ss)
#define NQKV (3*Hh*Ee)   /* 2304 */

// ---------------------------------------------------------------------------
// Scratch (device globals: allocation-free rule)
// ---------------------------------------------------------------------------
__device__ __align__(16) __nv_bfloat16 g_xh[BS*Dd],   g_xl[BS*Dd];   // x split [M][K]
__device__ __align__(16) __nv_bfloat16 g_wh[NQKV*Dd], g_wl[NQKV*Dd]; // qkv W [N][K]
__device__ __align__(16) __nv_bfloat16 g_ah[BS*Dd],   g_al[BS*Dd];   // attn out split [M][K]
__device__ __align__(16) __nv_bfloat16 g_ph[Dd*Dd],   g_pl[Dd*Dd];   // Wp [N][K]
// q/k/v bf16 hi/lo, layout [B,H,S,E]
__device__ __align__(16) __nv_bfloat16 g_qh[Bb*Hh*Ss*Ee], g_ql[Bb*Hh*Ss*Ee];
__device__ __align__(16) __nv_bfloat16 g_kh[Bb*Hh*Ss*Ee], g_kl[Bb*Hh*Ss*Ee];
__device__ __align__(16) __nv_bfloat16 g_vh[Bb*Hh*Ss*Ee], g_vl[Bb*Hh*Ss*Ee];

// ---------------------------------------------------------------------------
// PTX helpers (compute_103-safe: mma.sync / ldmatrix / cp.async only)
// ---------------------------------------------------------------------------
__device__ __forceinline__ uint32_t smem_u32(const void* p) {
    uint32_t a;
    asm("{ .reg .u64 t; cvta.to.shared.u64 t, %1; cvt.u32.u64 %0, t; }"
        : "=r"(a) : "l"(p));
    return a;
}
__device__ __forceinline__ void ldsm4(uint32_t r[4], uint32_t addr) {
    asm volatile("ldmatrix.sync.aligned.m8n8.x4.shared.b16 {%0,%1,%2,%3}, [%4];"
        : "=r"(r[0]), "=r"(r[1]), "=r"(r[2]), "=r"(r[3]) : "r"(addr));
}
__device__ __forceinline__ void ldsm4t(uint32_t r[4], uint32_t addr) {
    asm volatile("ldmatrix.sync.aligned.m8n8.x4.trans.shared.b16 {%0,%1,%2,%3}, [%4];"
        : "=r"(r[0]), "=r"(r[1]), "=r"(r[2]), "=r"(r[3]) : "r"(addr));
}
__device__ __forceinline__ void mma16816(float d[4], const uint32_t a[4],
                                         uint32_t b0, uint32_t b1) {
    asm volatile(
        "mma.sync.aligned.m16n8k16.row.col.f32.bf16.bf16.f32 "
        "{%0,%1,%2,%3}, {%4,%5,%6,%7}, {%8,%9}, {%0,%1,%2,%3};"
        : "+f"(d[0]), "+f"(d[1]), "+f"(d[2]), "+f"(d[3])
        : "r"(a[0]), "r"(a[1]), "r"(a[2]), "r"(a[3]), "r"(b0), "r"(b1));
}
__device__ __forceinline__ float ex2f(float x) {
    float y; asm("ex2.approx.f32 %0, %1;" : "=f"(y) : "f"(x)); return y;
}
__device__ __forceinline__ void split2(float a, float b, uint32_t& hi, uint32_t& lo) {
    __nv_bfloat16 ha = __float2bfloat16(a), hb = __float2bfloat16(b);
    __nv_bfloat16 la = __float2bfloat16(a - __bfloat162float(ha));
    __nv_bfloat16 lb = __float2bfloat16(b - __bfloat162float(hb));
    __nv_bfloat162 hv; hv.x = ha; hv.y = hb;
    __nv_bfloat162 lv; lv.x = la; lv.y = lb;
    hi = *(uint32_t*)&hv; lo = *(uint32_t*)&lv;
}
#define CP16(sa, ga) asm volatile("cp.async.cg.shared.global [%0], [%1], 16;" :: "r"(sa), "l"(ga))
#define CP_COMMIT()  asm volatile("cp.async.commit_group;" ::: "memory")
#define CP_WAIT1()   asm volatile("cp.async.wait_group 1;" ::: "memory")
#define CP_WAIT0()   asm volatile("cp.async.wait_group 0;" ::: "memory")

// ---------------------------------------------------------------------------
// Conversion kernels: fp32 -> bf16 hi/lo split
// ---------------------------------------------------------------------------
__global__ void cvt_x(const float* __restrict__ x) {
    for (int i = blockIdx.x*blockDim.x + threadIdx.x; i < BS*Dd; i += gridDim.x*blockDim.x) {
        float f = x[i];
        __nv_bfloat16 h = __float2bfloat16(f);
        g_xh[i] = h;
        g_xl[i] = __float2bfloat16(f - __bfloat162float(h));
    }
}
__global__ void cvt_wqkv(const float* __restrict__ Wq, const float* __restrict__ Wk,
                         const float* __restrict__ Wv) {
    for (int i = blockIdx.x*blockDim.x + threadIdx.x; i < NQKV*Dd; i += gridDim.x*blockDim.x) {
        int n = i / Dd, k = i - n * Dd;
        int which = n / (Hh*Ee);
        int rr = n - which * (Hh*Ee);
        int h = rr >> 6, e = rr & 63;
        const float* W = (which == 0) ? Wq : (which == 1) ? Wk : Wv;
        float f = W[(h*Dd + k)*Ee + e];
        __nv_bfloat16 hb = __float2bfloat16(f);
        g_wh[i] = hb;
        g_wl[i] = __float2bfloat16(f - __bfloat162float(hb));
    }
}
__global__ void cvt_wp(const float* __restrict__ Wp) {
    for (int i = blockIdx.x*blockDim.x + threadIdx.x; i < Dd*Dd; i += gridDim.x*blockDim.x) {
        int n = i / Dd, k = i - n * Dd;
        float f = Wp[k*Dd + n];
        __nv_bfloat16 h = __float2bfloat16(f);
        g_ph[i] = h;
        g_pl[i] = __float2bfloat16(f - __bfloat162float(h));
    }
}

// ---------------------------------------------------------------------------
// GEMM via mma.sync bf16x3.  C[M][N] = A[M][K] * B[N][K]^T (+bias epilogue).
// CTA 128x128, 4 warps (2m x 2n), warp tile 64x64, K-chunk 32, 2-stage cp.async.
// MODE 0: QKV proj -> writes bf16 hi/lo q/k/v arrays (+bias).
// MODE 1: out proj -> fp32 out (+bp, passed via bq).
// ---------------------------------------------------------------------------
#define GST 40                        /* smem row stride in bf16 elems */
#define GT  (128*GST*2)               /* one tile: 10240 B */
#define GSTAGE (4*GT)                 /* Ah,Al,Bh,Bl per stage: 40960 B */
#define GEMM_SMEM (2*GSTAGE)          /* 81920 B */
#define NCHUNK (Dd/32)                /* 24 */

template<int MODE>
__global__ __launch_bounds__(128, 2) void gemm_mma(
    const float* __restrict__ bq, const float* __restrict__ bk,
    const float* __restrict__ bv, float* __restrict__ outp)
{
    extern __shared__ char smem[];
    const uint32_t sbase = smem_u32(smem);

    const __nv_bfloat16* __restrict__ Ah = (MODE == 0) ? g_xh : g_ah;
    const __nv_bfloat16* __restrict__ Al = (MODE == 0) ? g_xl : g_al;
    const __nv_bfloat16* __restrict__ Bh = (MODE == 0) ? g_wh : g_ph;
    const __nv_bfloat16* __restrict__ Bl = (MODE == 0) ? g_wl : g_pl;

    const int m0 = blockIdx.x * 128;
    const int n0 = blockIdx.y * 128;
    const int tid  = threadIdx.x;
    const int wid  = tid >> 5, lane = tid & 31;
    const int wm = wid & 1, wn = wid >> 1;   // warp tile: rows wm*64, cols wn*64

    float acc[4][8][4] = {};                 // [mt][nf][4]

    auto issue = [&](int s) {
        const int buf = s & 1;
        const uint32_t sd = sbase + buf * GSTAGE;
        const int k0 = s * 32;
        #pragma unroll
        for (int it = 0; it < 4; it++) {
            int u = tid + it * 128;          // 0..511
            int r = u >> 2, c8 = (u & 3) * 8;
            uint32_t off = (uint32_t)(r * GST + c8) * 2;
            size_t ai = (size_t)(m0 + r) * Dd + k0 + c8;
            size_t bi = (size_t)(n0 + r) * Dd + k0 + c8;
            CP16(sd + 0*GT + off, Ah + ai);
            CP16(sd + 1*GT + off, Al + ai);
            CP16(sd + 2*GT + off, Bh + bi);
            CP16(sd + 3*GT + off, Bl + bi);
        }
    };

    issue(0); CP_COMMIT();

    for (int s = 0; s < NCHUNK; s++) {
        if (s + 1 < NCHUNK) { issue(s + 1); CP_COMMIT(); CP_WAIT1(); }
        else                { CP_WAIT0(); }
        __syncthreads();

        const uint32_t sd  = sbase + (s & 1) * GSTAGE;
        const uint32_t sAh = sd, sAl = sd + GT, sBh = sd + 2*GT, sBl = sd + 3*GT;

        #pragma unroll
        for (int kk = 0; kk < 2; kk++) {
            uint32_t ah[4][4], al[4][4];
            uint32_t a_off = (uint32_t)((wm*64 + (lane & 15)) * GST + kk*16 + (lane >> 4)*8) * 2;
            #pragma unroll
            for (int mt = 0; mt < 4; mt++) {
                ldsm4(ah[mt], sAh + a_off + mt*16*GST*2);
                ldsm4(al[mt], sAl + a_off + mt*16*GST*2);
            }
            uint32_t bh[8][2], bl[8][2];
            uint32_t b_off = (uint32_t)((wn*64 + (lane & 15)) * GST + kk*16 + (lane >> 4)*8) * 2;
            #pragma unroll
            for (int half = 0; half < 4; half++) {
                uint32_t t[4];
                ldsm4(t, sBh + b_off + half*16*GST*2);
                bh[half*2+0][0] = t[0]; bh[half*2+0][1] = t[2];
                bh[half*2+1][0] = t[1]; bh[half*2+1][1] = t[3];
                ldsm4(t, sBl + b_off + half*16*GST*2);
                bl[half*2+0][0] = t[0]; bl[half*2+0][1] = t[2];
                bl[half*2+1][0] = t[1]; bl[half*2+1][1] = t[3];
            }
            #pragma unroll
            for (int mt = 0; mt < 4; mt++)
                #pragma unroll
                for (int nf = 0; nf < 8; nf++) {
                    mma16816(acc[mt][nf], ah[mt], bh[nf][0], bh[nf][1]);
                    mma16816(acc[mt][nf], ah[mt], bl[nf][0], bl[nf][1]);
                    mma16816(acc[mt][nf], al[mt], bh[nf][0], bh[nf][1]);
                }
        }
        __syncthreads();
    }

    // ---- epilogue ----
    #pragma unroll
    for (int mt = 0; mt < 4; mt++) {
        const int m = m0 + wm*64 + mt*16 + (lane >> 2);
        #pragma unroll
        for (int nf = 0; nf < 8; nf++) {
            if (MODE == 0) {
                int ng = n0 + wn*64 + nf*8;
                int which = ng / (Hh*Ee);
                int rr = ng - which * (Hh*Ee);
                int h = rr >> 6;
                int e0 = (rr & 63) + (lane & 3)*2;
                __nv_bfloat16* dh = (which == 0) ? g_qh : (which == 1) ? g_kh : g_vh;
                __nv_bfloat16* dl = (which == 0) ? g_ql : (which == 1) ? g_kl : g_vl;
                const float* bsrc = (which == 0) ? bq : (which == 1) ? bk : bv;
                float b0f = bsrc[h*Ee + e0], b1f = bsrc[h*Ee + e0 + 1];
                int b = m >> 11, sI = m & 2047;
                size_t base = (((size_t)(b*Hh + h)) * Ss + sI) * Ee + e0;
                uint32_t hw, lw;
                split2(acc[mt][nf][0] + b0f, acc[mt][nf][1] + b1f, hw, lw);
                *(uint32_t*)(dh + base) = hw;
                *(uint32_t*)(dl + base) = lw;
                split2(acc[mt][nf][2] + b0f, acc[mt][nf][3] + b1f, hw, lw);
                *(uint32_t*)(dh + base + 8*Ee) = hw;   // row m+8 (same b,h)
                *(uint32_t*)(dl + base + 8*Ee) = lw;
            } else {
                int nn = n0 + wn*64 + nf*8 + (lane & 3)*2;
                float b0f = bq[nn], b1f = bq[nn + 1];   // bq carries bp
                float2 v0 = { acc[mt][nf][0] + b0f, acc[mt][nf][1] + b1f };
                float2 v1 = { acc[mt][nf][2] + b0f, acc[mt][nf][3] + b1f };
                *(float2*)(outp + (size_t)m*Dd + nn)       = v0;
                *(float2*)(outp + (size_t)(m+8)*Dd + nn)   = v1;
            }
        }
    }
}

// ---------------------------------------------------------------------------
// Flash attention, register-resident softmax.
// CTA: 128 q-rows, 128 threads (4 warps x 32 q-rows x all 64 keys).
// K/V bf16 split double-buffered via cp.async; Q-hi in regs, Q-lo in smem.
// ---------------------------------------------------------------------------
#define AST 72                 /* bf16 row stride (64+8) */
#define SUBB (64*AST*2)        /* one 64x64 bf16 subtile: 9216 B */
#define STG (4*SUBB)           /* stage: Kh,Kl,Vh,Vl = 36864 B */
#define QB  (128*AST*2)        /* one 128x64 Q array: 18432 B */
#define OFF_Q (2*STG)          /* 73728 */
#define ATTN_SMEM (OFF_Q + 2*QB)  /* 110592 B */

__global__ __launch_bounds__(128) void attn_mma()
{
    extern __shared__ char smem[];
    const uint32_t sbase = smem_u32(smem);
    const int q0 = blockIdx.x * 128;
    const int h  = blockIdx.y;
    const int b  = blockIdx.z;
    const int tid = threadIdx.x;
    const int wid = tid >> 5, lane = tid & 31;
    const size_t gbase = (size_t)(b*Hh + h) * Ss * Ee;
    const __nv_bfloat16* __restrict__ qhp = g_qh + gbase;
    const __nv_bfloat16* __restrict__ qlp = g_ql + gbase;
    const __nv_bfloat16* __restrict__ khp = g_kh + gbase;
    const __nv_bfloat16* __restrict__ klp = g_kl + gbase;
    const __nv_bfloat16* __restrict__ vhp = g_vh + gbase;
    const __nv_bfloat16* __restrict__ vlp = g_vl + gbase;

    // ---- stage Q (hi/lo, 128 rows x 64 cols = 8 x 16B chunks per row) ----
    #pragma unroll
    for (int i = 0; i < 16; i++) {
        int arr = i >> 3;                 // 0 hi (i<8), 1 lo
        int rem = (i & 7)*128 + tid;      // 0..1023
        int r = rem >> 3, c16 = rem & 7;
        uint32_t sa = sbase + OFF_Q + arr*QB + (uint32_t)r*(AST*2) + c16*16;
        const __nv_bfloat16* gp = (arr ? qlp : qhp) + (q0 + r)*Ee + c16*8;
        CP16(sa, gp);
    }
    CP_COMMIT();

    // ---- prefetch KV tile 0 into stage 0 ----
    #pragma unroll
    for (int i = 0; i < 16; i++) {
        int sub = i >> 2;                 // 0 Kh, 1 Kl, 2 Vh, 3 Vl
        int rem = (i & 3)*128 + tid;
        int r = rem >> 3, c16 = rem & 7;
        const __nv_bfloat16* gp =
            (sub == 0 ? khp : sub == 1 ? klp : sub == 2 ? vhp : vlp) + r*Ee + c16*8;
        CP16(sbase + sub*SUBB + (uint32_t)r*(AST*2) + c16*16, gp);
    }
    CP_COMMIT();

    CP_WAIT1();            // Q ready (KV0 may still be in flight)
    __syncthreads();

    // ---- Q-hi fragments in regs (2 msub x 4 k16) ----
    uint32_t qh[2][4][4];
    uint32_t qoff[2];
    #pragma unroll
    for (int ms = 0; ms < 2; ms++) {
        qoff[ms] = (uint32_t)(wid*32 + ms*16 + (lane & 15))*(AST*2) + (lane >> 4)*16;
        #pragma unroll
        for (int kk = 0; kk < 4; kk++)
            ldsm4(qh[ms][kk], sbase + OFF_Q + qoff[ms] + kk*32);
    }

    float o[2][8][4] = {};
    float mm[2][2], ll[2][2];
    #pragma unroll
    for (int ms = 0; ms < 2; ms++) { mm[ms][0] = mm[ms][1] = -1e30f; ll[ms][0] = ll[ms][1] = 0.f; }
    const float Cc = 0.18033688011112042f;   // 0.125 * log2(e)

    for (int s = 0; s < Ss/64; s++) {
        if (s + 1 < Ss/64) {
            const uint32_t stn = sbase + ((s+1) & 1)*STG;
            const int k0 = (s+1)*64;
            #pragma unroll
            for (int i = 0; i < 16; i++) {
                int sub = i >> 2;
                int rem = (i & 3)*128 + tid;
                int r = rem >> 3, c16 = rem & 7;
                const __nv_bfloat16* gp =
                    (sub == 0 ? khp : sub == 1 ? klp : sub == 2 ? vhp : vlp)
                    + (k0 + r)*Ee + c16*8;
                CP16(stn + sub*SUBB + (uint32_t)r*(AST*2) + c16*16, gp);
            }
            CP_COMMIT();
            CP_WAIT1();
        } else {
            CP_WAIT0();
        }
        __syncthreads();

        const uint32_t st = sbase + (s & 1)*STG;

        // ---- S = Q K^T (bf16x3) ----
        float sacc[2][8][4];
        #pragma unroll
        for (int ms = 0; ms < 2; ms++)
            #pragma unroll
            for (int nf = 0; nf < 8; nf++)
                #pragma unroll
                for (int j = 0; j < 4; j++) sacc[ms][nf][j] = 0.f;

        uint32_t kbase = (uint32_t)(lane & 15)*(AST*2) + (lane >> 4)*16;
        #pragma unroll
        for (int kk = 0; kk < 4; kk++) {
            uint32_t qlo[2][4];
            ldsm4(qlo[0], sbase + OFF_Q + QB + qoff[0] + kk*32);
            ldsm4(qlo[1], sbase + OFF_Q + QB + qoff[1] + kk*32);
            #pragma unroll
            for (int g = 0; g < 4; g++) {
                uint32_t th[4], tl[4];
                uint32_t ad = st + kbase + (uint32_t)g*16*(AST*2) + kk*32;
                ldsm4(th, ad);            // K hi
                ldsm4(tl, ad + SUBB);     // K lo
                #pragma unroll
                for (int ms = 0; ms < 2; ms++) {
                    mma16816(sacc[ms][2*g],   qh[ms][kk], th[0], th[2]);
                    mma16816(sacc[ms][2*g+1], qh[ms][kk], th[1], th[3]);
                    mma16816(sacc[ms][2*g],   qh[ms][kk], tl[0], tl[2]);
                    mma16816(sacc[ms][2*g+1], qh[ms][kk], tl[1], tl[3]);
                    mma16816(sacc[ms][2*g],   qlo[ms], th[0], th[2]);
                    mma16816(sacc[ms][2*g+1], qlo[ms], th[1], th[3]);
                }
            }
        }

        // ---- online softmax (registers; rows warp-local) + P frags ----
        uint32_t pfh[2][4][4], pfl[2][4][4];
        float al[2][2];
        #pragma unroll
        for (int ms = 0; ms < 2; ms++) {
            float r0 = -1e30f, r1 = -1e30f;
            #pragma unroll
            for (int nf = 0; nf < 8; nf++) {
                r0 = fmaxf(r0, fmaxf(sacc[ms][nf][0], sacc[ms][nf][1]));
                r1 = fmaxf(r1, fmaxf(sacc[ms][nf][2], sacc[ms][nf][3]));
            }
            r0 = fmaxf(r0, __shfl_xor_sync(0xffffffffu, r0, 1));
            r0 = fmaxf(r0, __shfl_xor_sync(0xffffffffu, r0, 2));
            r1 = fmaxf(r1, __shfl_xor_sync(0xffffffffu, r1, 1));
            r1 = fmaxf(r1, __shfl_xor_sync(0xffffffffu, r1, 2));
            float mn0 = fmaxf(mm[ms][0], r0), mn1 = fmaxf(mm[ms][1], r1);
            al[ms][0] = ex2f((mm[ms][0] - mn0)*Cc);
            al[ms][1] = ex2f((mm[ms][1] - mn1)*Cc);
            mm[ms][0] = mn0; mm[ms][1] = mn1;

            float ps0 = 0.f, ps1 = 0.f;
            #pragma unroll
            for (int nf = 0; nf < 8; nf++) {
                sacc[ms][nf][0] = ex2f((sacc[ms][nf][0] - mn0)*Cc);
                sacc[ms][nf][1] = ex2f((sacc[ms][nf][1] - mn0)*Cc);
                sacc[ms][nf][2] = ex2f((sacc[ms][nf][2] - mn1)*Cc);
                sacc[ms][nf][3] = ex2f((sacc[ms][nf][3] - mn1)*Cc);
                ps0 += sacc[ms][nf][0] + sacc[ms][nf][1];
                ps1 += sacc[ms][nf][2] + sacc[ms][nf][3];
            }
            ps0 += __shfl_xor_sync(0xffffffffu, ps0, 1);
            ps0 += __shfl_xor_sync(0xffffffffu, ps0, 2);
            ps1 += __shfl_xor_sync(0xffffffffu, ps1, 1);
            ps1 += __shfl_xor_sync(0xffffffffu, ps1, 2);
            ll[ms][0] = ll[ms][0]*al[ms][0] + ps0;
            ll[ms][1] = ll[ms][1]*al[ms][1] + ps1;

            #pragma unroll
            for (int kk = 0; kk < 4; kk++) {
                int n0f = 2*kk, n1f = 2*kk + 1;
                split2(sacc[ms][n0f][0], sacc[ms][n0f][1], pfh[ms][kk][0], pfl[ms][kk][0]);
                split2(sacc[ms][n0f][2], sacc[ms][n0f][3], pfh[ms][kk][1], pfl[ms][kk][1]);
                split2(sacc[ms][n1f][0], sacc[ms][n1f][1], pfh[ms][kk][2], pfl[ms][kk][2]);
                split2(sacc[ms][n1f][2], sacc[ms][n1f][3], pfh[ms][kk][3], pfl[ms][kk][3]);
            }
        }

        // ---- rescale O, then O += P V (bf16x3) ----
        #pragma unroll
        for (int ms = 0; ms < 2; ms++)
            #pragma unroll
            for (int nf = 0; nf < 8; nf++) {
                o[ms][nf][0] *= al[ms][0]; o[ms][nf][1] *= al[ms][0];
                o[ms][nf][2] *= al[ms][1]; o[ms][nf][3] *= al[ms][1];
            }
        #pragma unroll
        for (int kk = 0; kk < 4; kk++) {
            uint32_t vb = st + 2*SUBB + (uint32_t)(kk*16 + (lane & 15))*(AST*2)
                          + (lane >> 4)*16;
            #pragma unroll
            for (int g = 0; g < 4; g++) {          // e16 groups
                uint32_t th[4], tl[4];
                ldsm4t(th, vb + g*32);             // V hi
                ldsm4t(tl, vb + SUBB + g*32);      // V lo
                #pragma unroll
                for (int ms = 0; ms < 2; ms++) {
                    mma16816(o[ms][2*g],   pfh[ms][kk], th[0], th[1]);
                    mma16816(o[ms][2*g+1], pfh[ms][kk], th[2], th[3]);
                    mma16816(o[ms][2*g],   pfh[ms][kk], tl[0], tl[1]);
                    mma16816(o[ms][2*g+1], pfh[ms][kk], tl[2], tl[3]);
                    mma16816(o[ms][2*g],   pfl[ms][kk], th[0], th[1]);
                    mma16816(o[ms][2*g+1], pfl[ms][kk], th[2], th[3]);
                }
            }
        }
        __syncthreads();   // stage fully consumed before next iter's issue
    }

    // ---- normalize + store bf16 split directly (feeds proj GEMM) ----
    #pragma unroll
    for (int ms = 0; ms < 2; ms++) {
        const int r0i = wid*32 + ms*16 + (lane >> 2);
        float inv0 = 1.0f / ll[ms][0], inv1 = 1.0f / ll[ms][1];
        #pragma unroll
        for (int nf = 0; nf < 8; nf++) {
            int e = nf*8 + (lane & 3)*2;
            size_t i0 = ((size_t)(b*Ss + q0 + r0i)*Hh + h)*Ee + e;
            size_t i1 = i0 + (size_t)8*Hh*Ee;
            uint32_t hw, lw;
            split2(o[ms][nf][0]*inv0, o[ms][nf][1]*inv0, hw, lw);
            *(uint32_t*)(g_ah + i0) = hw;
            *(uint32_t*)(g_al + i0) = lw;
            split2(o[ms][nf][2]*inv1, o[ms][nf][3]*inv1, hw, lw);
            *(uint32_t*)(g_ah + i1) = hw;
            *(uint32_t*)(g_al + i1) = lw;
        }
    }
}

// ---------------------------------------------------------------------------
extern "C" void kernel_launch(void* const* d_in, const int* in_sizes, int n_in,
                              void* d_out, int out_size)
{
    const float* x  = (const float*)d_in[0];
    const float* Wq = (const float*)d_in[1];
    const float* bq = (const float*)d_in[2];
    const float* Wk = (const float*)d_in[3];
    const float* bk = (const float*)d_in[4];
    const float* Wv = (const float*)d_in[5];
    const float* bv = (const float*)d_in[6];
    const float* Wp = (const float*)d_in[7];
    const float* bp = (const float*)d_in[8];
    float* out = (float*)d_out;

    cudaFuncSetAttribute(gemm_mma<0>, cudaFuncAttributeMaxDynamicSharedMemorySize, GEMM_SMEM);
    cudaFuncSetAttribute(gemm_mma<1>, cudaFuncAttributeMaxDynamicSharedMemorySize, GEMM_SMEM);
    cudaFuncSetAttribute(attn_mma,    cudaFuncAttributeMaxDynamicSharedMemorySize, ATTN_SMEM);

    cvt_x<<<2048, 256>>>(x);
    cvt_wqkv<<<1024, 256>>>(Wq, Wk, Wv);
    gemm_mma<0><<<dim3(BS/128, NQKV/128), 128, GEMM_SMEM>>>(bq, bk, bv, nullptr);
    attn_mma<<<dim3(Ss/128, Hh, Bb), 128, ATTN_SMEM>>>();
    cvt_wp<<<512, 256>>>(Wp);
    gemm_mma<1><<<dim3(BS/128, Dd/128), 128, GEMM_SMEM>>>(bp, nullptr, nullptr, out);
}

// round 8
// speedup vs baseline: 4.1695x; 1.3690x over previous
#include <cuda_runtime.h>
#include <cuda_fp16.h>
#include <math.h>
#include <stdint.h>

#define Bb 4
#define Ss 2048
#define Dd 768
#define Hh 12
#define Ee 64
#define BS (Bb*Ss)
#define NQKV (3*Hh*Ee)   /* 2304 */

// ---------------------------------------------------------------------------
// Scratch (device globals: allocation-free rule)
// Activations: single fp16.  Weights / K / V: fp16 hi+lo.
// ---------------------------------------------------------------------------
__device__ __align__(16) __half g_x[BS*Dd];                    // x fp16 [M][K]
__device__ __align__(16) __half g_wh[NQKV*Dd], g_wl[NQKV*Dd];  // qkv W [N][K]
__device__ __align__(16) __half g_a[BS*Dd];                    // attn out fp16 [M][K]
__device__ __align__(16) __half g_ph[Dd*Dd],  g_pl[Dd*Dd];     // Wp [N][K]
// q single; k/v hi+lo.  layout [B,H,S,E]
__device__ __align__(16) __half g_q[Bb*Hh*Ss*Ee];
__device__ __align__(16) __half g_kh[Bb*Hh*Ss*Ee], g_kl[Bb*Hh*Ss*Ee];
__device__ __align__(16) __half g_vh[Bb*Hh*Ss*Ee], g_vl[Bb*Hh*Ss*Ee];

// ---------------------------------------------------------------------------
// PTX helpers (compute_103-safe: mma.sync / ldmatrix / cp.async only)
// ---------------------------------------------------------------------------
__device__ __forceinline__ uint32_t smem_u32(const void* p) {
    uint32_t a;
    asm("{ .reg .u64 t; cvta.to.shared.u64 t, %1; cvt.u32.u64 %0, t; }"
        : "=r"(a) : "l"(p));
    return a;
}
__device__ __forceinline__ void ldsm4(uint32_t r[4], uint32_t addr) {
    asm volatile("ldmatrix.sync.aligned.m8n8.x4.shared.b16 {%0,%1,%2,%3}, [%4];"
        : "=r"(r[0]), "=r"(r[1]), "=r"(r[2]), "=r"(r[3]) : "r"(addr));
}
__device__ __forceinline__ void ldsm4t(uint32_t r[4], uint32_t addr) {
    asm volatile("ldmatrix.sync.aligned.m8n8.x4.trans.shared.b16 {%0,%1,%2,%3}, [%4];"
        : "=r"(r[0]), "=r"(r[1]), "=r"(r[2]), "=r"(r[3]) : "r"(addr));
}
__device__ __forceinline__ void mma16816(float d[4], const uint32_t a[4],
                                         uint32_t b0, uint32_t b1) {
    asm volatile(
        "mma.sync.aligned.m16n8k16.row.col.f32.f16.f16.f32 "
        "{%0,%1,%2,%3}, {%4,%5,%6,%7}, {%8,%9}, {%0,%1,%2,%3};"
        : "+f"(d[0]), "+f"(d[1]), "+f"(d[2]), "+f"(d[3])
        : "r"(a[0]), "r"(a[1]), "r"(a[2]), "r"(a[3]), "r"(b0), "r"(b1));
}
__device__ __forceinline__ float ex2f(float x) {
    float y; asm("ex2.approx.f32 %0, %1;" : "=f"(y) : "f"(x)); return y;
}
__device__ __forceinline__ uint32_t pack2h(float a, float b) {
    __half2 v = __floats2half2_rn(a, b);
    return *(uint32_t*)&v;
}
__device__ __forceinline__ void split2h(float a, float b, uint32_t& hi, uint32_t& lo) {
    __half ha = __float2half_rn(a), hb = __float2half_rn(b);
    __half la = __float2half_rn(a - __half2float(ha));
    __half lb = __float2half_rn(b - __half2float(hb));
    __half2 hv = __halves2half2(ha, hb);
    __half2 lv = __halves2half2(la, lb);
    hi = *(uint32_t*)&hv; lo = *(uint32_t*)&lv;
}
#define CP16(sa, ga) asm volatile("cp.async.cg.shared.global [%0], [%1], 16;" :: "r"(sa), "l"(ga))
#define CP_COMMIT()  asm volatile("cp.async.commit_group;" ::: "memory")
#define CP_WAIT1()   asm volatile("cp.async.wait_group 1;" ::: "memory")
#define CP_WAIT0()   asm volatile("cp.async.wait_group 0;" ::: "memory")

// ---------------------------------------------------------------------------
// Conversion kernels
// ---------------------------------------------------------------------------
__global__ void cvt_x(const float* __restrict__ x) {
    for (int i = blockIdx.x*blockDim.x + threadIdx.x; i < BS*Dd; i += gridDim.x*blockDim.x)
        g_x[i] = __float2half_rn(x[i]);
}
__global__ void cvt_wqkv(const float* __restrict__ Wq, const float* __restrict__ Wk,
                         const float* __restrict__ Wv) {
    for (int i = blockIdx.x*blockDim.x + threadIdx.x; i < NQKV*Dd; i += gridDim.x*blockDim.x) {
        int n = i / Dd, k = i - n * Dd;
        int which = n / (Hh*Ee);
        int rr = n - which * (Hh*Ee);
        int h = rr >> 6, e = rr & 63;
        const float* W = (which == 0) ? Wq : (which == 1) ? Wk : Wv;
        float f = W[(h*Dd + k)*Ee + e];
        __half hb = __float2half_rn(f);
        g_wh[i] = hb;
        g_wl[i] = __float2half_rn(f - __half2float(hb));
    }
}
__global__ void cvt_wp(const float* __restrict__ Wp) {
    for (int i = blockIdx.x*blockDim.x + threadIdx.x; i < Dd*Dd; i += gridDim.x*blockDim.x) {
        int n = i / Dd, k = i - n * Dd;
        float f = Wp[k*Dd + n];
        __half h = __float2half_rn(f);
        g_ph[i] = h;
        g_pl[i] = __float2half_rn(f - __half2float(h));
    }
}

// ---------------------------------------------------------------------------
// GEMM via mma.sync fp16x2.  C[M][N] = A[M][K] * B[N][K]^T (+bias epilogue).
// A single fp16; B hi+lo.  CTA 128x128, 4 warps (2m x 2n), warp 64x64,
// K-chunk 32, 2-stage cp.async.
// MODE 0: QKV proj -> q single / k,v hi+lo (+bias). MODE 1: out proj fp32.
// ---------------------------------------------------------------------------
#define GST 40                        /* smem row stride in fp16 elems */
#define GT  (128*GST*2)               /* one tile: 10240 B */
#define GSTAGE (3*GT)                 /* A,Bh,Bl per stage: 30720 B */
#define GEMM_SMEM (2*GSTAGE)          /* 61440 B */
#define NCHUNK (Dd/32)                /* 24 */

template<int MODE>
__global__ __launch_bounds__(128, 2) void gemm_mma(
    const float* __restrict__ bq, const float* __restrict__ bk,
    const float* __restrict__ bv, float* __restrict__ outp)
{
    extern __shared__ char smem[];
    const uint32_t sbase = smem_u32(smem);

    const __half* __restrict__ Aa = (MODE == 0) ? g_x  : g_a;
    const __half* __restrict__ Bh = (MODE == 0) ? g_wh : g_ph;
    const __half* __restrict__ Bl = (MODE == 0) ? g_wl : g_pl;

    const int m0 = blockIdx.x * 128;
    const int n0 = blockIdx.y * 128;
    const int tid  = threadIdx.x;
    const int wid  = tid >> 5, lane = tid & 31;
    const int wm = wid & 1, wn = wid >> 1;   // warp tile: rows wm*64, cols wn*64

    float acc[4][8][4] = {};                 // [mt][nf][4]

    auto issue = [&](int s) {
        const int buf = s & 1;
        const uint32_t sd = sbase + buf * GSTAGE;
        const int k0 = s * 32;
        #pragma unroll
        for (int it = 0; it < 4; it++) {
            int u = tid + it * 128;          // 0..511
            int r = u >> 2, c8 = (u & 3) * 8;
            uint32_t off = (uint32_t)(r * GST + c8) * 2;
            size_t ai = (size_t)(m0 + r) * Dd + k0 + c8;
            size_t bi = (size_t)(n0 + r) * Dd + k0 + c8;
            CP16(sd + 0*GT + off, Aa + ai);
            CP16(sd + 1*GT + off, Bh + bi);
            CP16(sd + 2*GT + off, Bl + bi);
        }
    };

    issue(0); CP_COMMIT();

    for (int s = 0; s < NCHUNK; s++) {
        if (s + 1 < NCHUNK) { issue(s + 1); CP_COMMIT(); CP_WAIT1(); }
        else                { CP_WAIT0(); }
        __syncthreads();

        const uint32_t sd  = sbase + (s & 1) * GSTAGE;
        const uint32_t sA = sd, sBh = sd + GT, sBl = sd + 2*GT;

        #pragma unroll
        for (int kk = 0; kk < 2; kk++) {
            uint32_t af[4][4];
            uint32_t a_off = (uint32_t)((wm*64 + (lane & 15)) * GST + kk*16 + (lane >> 4)*8) * 2;
            #pragma unroll
            for (int mt = 0; mt < 4; mt++)
                ldsm4(af[mt], sA + a_off + mt*16*GST*2);

            uint32_t bh[8][2], bl[8][2];
            uint32_t b_off = (uint32_t)((wn*64 + (lane & 15)) * GST + kk*16 + (lane >> 4)*8) * 2;
            #pragma unroll
            for (int half = 0; half < 4; half++) {
                uint32_t t[4];
                ldsm4(t, sBh + b_off + half*16*GST*2);
                bh[half*2+0][0] = t[0]; bh[half*2+0][1] = t[2];
                bh[half*2+1][0] = t[1]; bh[half*2+1][1] = t[3];
                ldsm4(t, sBl + b_off + half*16*GST*2);
                bl[half*2+0][0] = t[0]; bl[half*2+0][1] = t[2];
                bl[half*2+1][0] = t[1]; bl[half*2+1][1] = t[3];
            }
            #pragma unroll
            for (int mt = 0; mt < 4; mt++)
                #pragma unroll
                for (int nf = 0; nf < 8; nf++) {
                    mma16816(acc[mt][nf], af[mt], bh[nf][0], bh[nf][1]);
                    mma16816(acc[mt][nf], af[mt], bl[nf][0], bl[nf][1]);
                }
        }
        __syncthreads();
    }

    // ---- epilogue ----
    #pragma unroll
    for (int mt = 0; mt < 4; mt++) {
        const int m = m0 + wm*64 + mt*16 + (lane >> 2);
        #pragma unroll
        for (int nf = 0; nf < 8; nf++) {
            if (MODE == 0) {
                int ng = n0 + wn*64 + nf*8;
                int which = ng / (Hh*Ee);
                int rr = ng - which * (Hh*Ee);
                int h = rr >> 6;
                int e0 = (rr & 63) + (lane & 3)*2;
                const float* bsrc = (which == 0) ? bq : (which == 1) ? bk : bv;
                float b0f = bsrc[h*Ee + e0], b1f = bsrc[h*Ee + e0 + 1];
                int b = m >> 11, sI = m & 2047;
                size_t base = (((size_t)(b*Hh + h)) * Ss + sI) * Ee + e0;
                float v00 = acc[mt][nf][0] + b0f, v01 = acc[mt][nf][1] + b1f;
                float v10 = acc[mt][nf][2] + b0f, v11 = acc[mt][nf][3] + b1f;
                if (which == 0) {
                    *(uint32_t*)(g_q + base)        = pack2h(v00, v01);
                    *(uint32_t*)(g_q + base + 8*Ee) = pack2h(v10, v11);
                } else {
                    __half* dh = (which == 1) ? g_kh : g_vh;
                    __half* dl = (which == 1) ? g_kl : g_vl;
                    uint32_t hw, lw;
                    split2h(v00, v01, hw, lw);
                    *(uint32_t*)(dh + base) = hw;
                    *(uint32_t*)(dl + base) = lw;
                    split2h(v10, v11, hw, lw);
                    *(uint32_t*)(dh + base + 8*Ee) = hw;
                    *(uint32_t*)(dl + base + 8*Ee) = lw;
                }
            } else {
                int nn = n0 + wn*64 + nf*8 + (lane & 3)*2;
                float b0f = bq[nn], b1f = bq[nn + 1];   // bq carries bp
                float2 v0 = { acc[mt][nf][0] + b0f, acc[mt][nf][1] + b1f };
                float2 v1 = { acc[mt][nf][2] + b0f, acc[mt][nf][3] + b1f };
                *(float2*)(outp + (size_t)m*Dd + nn)       = v0;
                *(float2*)(outp + (size_t)(m+8)*Dd + nn)   = v1;
            }
        }
    }
}

// ---------------------------------------------------------------------------
// Flash attention, register-resident softmax, fp16x2.
// CTA: 128 q-rows, 128 threads (4 warps x 32 q-rows x all 64 keys).
// Q single fp16 in regs; K/V hi+lo double-buffered via cp.async.
// ---------------------------------------------------------------------------
#define AST 72                 /* fp16 row stride (64+8) */
#define SUBB (64*AST*2)        /* one 64x64 fp16 subtile: 9216 B */
#define STG (4*SUBB)           /* stage: Kh,Kl,Vh,Vl = 36864 B */
#define QB  (128*AST*2)        /* 128x64 Q array: 18432 B */
#define OFF_Q (2*STG)          /* 73728 */
#define ATTN_SMEM (OFF_Q + QB) /* 92160 B */

__global__ __launch_bounds__(128) void attn_mma()
{
    extern __shared__ char smem[];
    const uint32_t sbase = smem_u32(smem);
    const int q0 = blockIdx.x * 128;
    const int h  = blockIdx.y;
    const int b  = blockIdx.z;
    const int tid = threadIdx.x;
    const int wid = tid >> 5, lane = tid & 31;
    const size_t gbase = (size_t)(b*Hh + h) * Ss * Ee;
    const __half* __restrict__ qp  = g_q  + gbase;
    const __half* __restrict__ khp = g_kh + gbase;
    const __half* __restrict__ klp = g_kl + gbase;
    const __half* __restrict__ vhp = g_vh + gbase;
    const __half* __restrict__ vlp = g_vl + gbase;

    // ---- stage Q (single, 128 rows x 64 cols = 8 x 16B chunks per row) ----
    #pragma unroll
    for (int i = 0; i < 8; i++) {
        int rem = i*128 + tid;            // 0..1023
        int r = rem >> 3, c16 = rem & 7;
        CP16(sbase + OFF_Q + (uint32_t)r*(AST*2) + c16*16, qp + (q0 + r)*Ee + c16*8);
    }
    CP_COMMIT();

    // ---- prefetch KV tile 0 into stage 0 ----
    #pragma unroll
    for (int i = 0; i < 16; i++) {
        int sub = i >> 2;                 // 0 Kh, 1 Kl, 2 Vh, 3 Vl
        int rem = (i & 3)*128 + tid;
        int r = rem >> 3, c16 = rem & 7;
        const __half* gp =
            (sub == 0 ? khp : sub == 1 ? klp : sub == 2 ? vhp : vlp) + r*Ee + c16*8;
        CP16(sbase + sub*SUBB + (uint32_t)r*(AST*2) + c16*16, gp);
    }
    CP_COMMIT();

    CP_WAIT1();            // Q ready (KV0 may still be in flight)
    __syncthreads();

    // ---- Q fragments in regs (2 msub x 4 k16) ----
    uint32_t qh[2][4][4];
    #pragma unroll
    for (int ms = 0; ms < 2; ms++) {
        uint32_t qo = (uint32_t)(wid*32 + ms*16 + (lane & 15))*(AST*2) + (lane >> 4)*16;
        #pragma unroll
        for (int kk = 0; kk < 4; kk++)
            ldsm4(qh[ms][kk], sbase + OFF_Q + qo + kk*32);
    }
    __syncthreads();

    float o[2][8][4] = {};
    float mm[2][2], ll[2][2];
    #pragma unroll
    for (int ms = 0; ms < 2; ms++) { mm[ms][0] = mm[ms][1] = -1e30f; ll[ms][0] = ll[ms][1] = 0.f; }
    const float Cc = 0.18033688011112042f;   // 0.125 * log2(e)

    for (int s = 0; s < Ss/64; s++) {
        if (s + 1 < Ss/64) {
            const uint32_t stn = sbase + ((s+1) & 1)*STG;
            const int k0 = (s+1)*64;
            #pragma unroll
            for (int i = 0; i < 16; i++) {
                int sub = i >> 2;
                int rem = (i & 3)*128 + tid;
                int r = rem >> 3, c16 = rem & 7;
                const __half* gp =
                    (sub == 0 ? khp : sub == 1 ? klp : sub == 2 ? vhp : vlp)
                    + (k0 + r)*Ee + c16*8;
                CP16(stn + sub*SUBB + (uint32_t)r*(AST*2) + c16*16, gp);
            }
            CP_COMMIT();
            CP_WAIT1();
        } else {
            CP_WAIT0();
        }
        __syncthreads();

        const uint32_t st = sbase + (s & 1)*STG;

        // ---- S = Q (Kh + Kl)^T ----
        float sacc[2][8][4];
        #pragma unroll
        for (int ms = 0; ms < 2; ms++)
            #pragma unroll
            for (int nf = 0; nf < 8; nf++)
                #pragma unroll
                for (int j = 0; j < 4; j++) sacc[ms][nf][j] = 0.f;

        uint32_t kbase = (uint32_t)(lane & 15)*(AST*2) + (lane >> 4)*16;
        #pragma unroll
        for (int kk = 0; kk < 4; kk++) {
            #pragma unroll
            for (int g = 0; g < 4; g++) {
                uint32_t th[4], tl[4];
                uint32_t ad = st + kbase + (uint32_t)g*16*(AST*2) + kk*32;
                ldsm4(th, ad);            // K hi
                ldsm4(tl, ad + SUBB);     // K lo
                #pragma unroll
                for (int ms = 0; ms < 2; ms++) {
                    mma16816(sacc[ms][2*g],   qh[ms][kk], th[0], th[2]);
                    mma16816(sacc[ms][2*g+1], qh[ms][kk], th[1], th[3]);
                    mma16816(sacc[ms][2*g],   qh[ms][kk], tl[0], tl[2]);
                    mma16816(sacc[ms][2*g+1], qh[ms][kk], tl[1], tl[3]);
                }
            }
        }

        // ---- online softmax (registers; rows warp-local) + P frags ----
        uint32_t pf[2][4][4];
        float al[2][2];
        #pragma unroll
        for (int ms = 0; ms < 2; ms++) {
            float r0 = -1e30f, r1 = -1e30f;
            #pragma unroll
            for (int nf = 0; nf < 8; nf++) {
                r0 = fmaxf(r0, fmaxf(sacc[ms][nf][0], sacc[ms][nf][1]));
                r1 = fmaxf(r1, fmaxf(sacc[ms][nf][2], sacc[ms][nf][3]));
            }
            r0 = fmaxf(r0, __shfl_xor_sync(0xffffffffu, r0, 1));
            r0 = fmaxf(r0, __shfl_xor_sync(0xffffffffu, r0, 2));
            r1 = fmaxf(r1, __shfl_xor_sync(0xffffffffu, r1, 1));
            r1 = fmaxf(r1, __shfl_xor_sync(0xffffffffu, r1, 2));
            float mn0 = fmaxf(mm[ms][0], r0), mn1 = fmaxf(mm[ms][1], r1);
            al[ms][0] = ex2f((mm[ms][0] - mn0)*Cc);
            al[ms][1] = ex2f((mm[ms][1] - mn1)*Cc);
            mm[ms][0] = mn0; mm[ms][1] = mn1;

            float ps0 = 0.f, ps1 = 0.f;
            #pragma unroll
            for (int nf = 0; nf < 8; nf++) {
                sacc[ms][nf][0] = ex2f((sacc[ms][nf][0] - mn0)*Cc);
                sacc[ms][nf][1] = ex2f((sacc[ms][nf][1] - mn0)*Cc);
                sacc[ms][nf][2] = ex2f((sacc[ms][nf][2] - mn1)*Cc);
                sacc[ms][nf][3] = ex2f((sacc[ms][nf][3] - mn1)*Cc);
                ps0 += sacc[ms][nf][0] + sacc[ms][nf][1];
                ps1 += sacc[ms][nf][2] + sacc[ms][nf][3];
            }
            ps0 += __shfl_xor_sync(0xffffffffu, ps0, 1);
            ps0 += __shfl_xor_sync(0xffffffffu, ps0, 2);
            ps1 += __shfl_xor_sync(0xffffffffu, ps1, 1);
            ps1 += __shfl_xor_sync(0xffffffffu, ps1, 2);
            ll[ms][0] = ll[ms][0]*al[ms][0] + ps0;
            ll[ms][1] = ll[ms][1]*al[ms][1] + ps1;

            #pragma unroll
            for (int kk = 0; kk < 4; kk++) {
                int n0f = 2*kk, n1f = 2*kk + 1;
                pf[ms][kk][0] = pack2h(sacc[ms][n0f][0], sacc[ms][n0f][1]);
                pf[ms][kk][1] = pack2h(sacc[ms][n0f][2], sacc[ms][n0f][3]);
                pf[ms][kk][2] = pack2h(sacc[ms][n1f][0], sacc[ms][n1f][1]);
                pf[ms][kk][3] = pack2h(sacc[ms][n1f][2], sacc[ms][n1f][3]);
            }
        }

        // ---- rescale O, then O += P (Vh + Vl) ----
        #pragma unroll
        for (int ms = 0; ms < 2; ms++)
            #pragma unroll
            for (int nf = 0; nf < 8; nf++) {
                o[ms][nf][0] *= al[ms][0]; o[ms][nf][1] *= al[ms][0];
                o[ms][nf][2] *= al[ms][1]; o[ms][nf][3] *= al[ms][1];
            }
        #pragma unroll
        for (int kk = 0; kk < 4; kk++) {
            uint32_t vb = st + 2*SUBB + (uint32_t)(kk*16 + (lane & 15))*(AST*2)
                          + (lane >> 4)*16;
            #pragma unroll
            for (int g = 0; g < 4; g++) {          // e16 groups
                uint32_t th[4], tl[4];
                ldsm4t(th, vb + g*32);             // V hi
                ldsm4t(tl, vb + SUBB + g*32);      // V lo
                #pragma unroll
                for (int ms = 0; ms < 2; ms++) {
                    mma16816(o[ms][2*g],   pf[ms][kk], th[0], th[1]);
                    mma16816(o[ms][2*g+1], pf[ms][kk], th[2], th[3]);
                    mma16816(o[ms][2*g],   pf[ms][kk], tl[0], tl[1]);
                    mma16816(o[ms][2*g+1], pf[ms][kk], tl[2], tl[3]);
                }
            }
        }
        __syncthreads();   // stage fully consumed before next iter's issue
    }

    // ---- normalize + store fp16 (feeds proj GEMM) ----
    #pragma unroll
    for (int ms = 0; ms < 2; ms++) {
        const int r0i = wid*32 + ms*16 + (lane >> 2);
        float inv0 = 1.0f / ll[ms][0], inv1 = 1.0f / ll[ms][1];
        #pragma unroll
        for (int nf = 0; nf < 8; nf++) {
            int e = nf*8 + (lane & 3)*2;
            size_t i0 = ((size_t)(b*Ss + q0 + r0i)*Hh + h)*Ee + e;
            size_t i1 = i0 + (size_t)8*Hh*Ee;
            *(uint32_t*)(g_a + i0) = pack2h(o[ms][nf][0]*inv0, o[ms][nf][1]*inv0);
            *(uint32_t*)(g_a + i1) = pack2h(o[ms][nf][2]*inv1, o[ms][nf][3]*inv1);
        }
    }
}

// ---------------------------------------------------------------------------
extern "C" void kernel_launch(void* const* d_in, const int* in_sizes, int n_in,
                              void* d_out, int out_size)
{
    const float* x  = (const float*)d_in[0];
    const float* Wq = (const float*)d_in[1];
    const float* bq = (const float*)d_in[2];
    const float* Wk = (const float*)d_in[3];
    const float* bk = (const float*)d_in[4];
    const float* Wv = (const float*)d_in[5];
    const float* bv = (const float*)d_in[6];
    const float* Wp = (const float*)d_in[7];
    const float* bp = (const float*)d_in[8];
    float* out = (float*)d_out;

    cudaFuncSetAttribute(gemm_mma<0>, cudaFuncAttributeMaxDynamicSharedMemorySize, GEMM_SMEM);
    cudaFuncSetAttribute(gemm_mma<1>, cudaFuncAttributeMaxDynamicSharedMemorySize, GEMM_SMEM);
    cudaFuncSetAttribute(attn_mma,    cudaFuncAttributeMaxDynamicSharedMemorySize, ATTN_SMEM);

    cvt_x<<<2048, 256>>>(x);
    cvt_wqkv<<<1024, 256>>>(Wq, Wk, Wv);
    gemm_mma<0><<<dim3(BS/128, NQKV/128), 128, GEMM_SMEM>>>(bq, bk, bv, nullptr);
    attn_mma<<<dim3(Ss/128, Hh, Bb), 128, ATTN_SMEM>>>();
    cvt_wp<<<512, 256>>>(Wp);
    gemm_mma<1><<<dim3(BS/128, Dd/128), 128, GEMM_SMEM>>>(bp, nullptr, nullptr, out);
}

// round 9
// speedup vs baseline: 6.8558x; 1.6443x over previous
#include <cuda_runtime.h>
#include <cuda_fp16.h>
#include <math.h>
#include <stdint.h>

#define Bb 4
#define Ss 2048
#define Dd 768
#define Hh 12
#define Ee 64
#define BS (Bb*Ss)
#define NQKV (3*Hh*Ee)   /* 2304 */

// ---------------------------------------------------------------------------
// Scratch (device globals: allocation-free rule).  Everything single fp16.
// ---------------------------------------------------------------------------
__device__ __align__(16) __half g_x[BS*Dd];        // x fp16 [M][K]
__device__ __align__(16) __half g_w[NQKV*Dd];      // qkv W [N][K]
__device__ __align__(16) __half g_a[BS*Dd];        // attn out fp16 [M][K]
__device__ __align__(16) __half g_p[Dd*Dd];        // Wp [N][K]
// q/k/v fp16, layout [B,H,S,E]
__device__ __align__(16) __half g_q[Bb*Hh*Ss*Ee];
__device__ __align__(16) __half g_k[Bb*Hh*Ss*Ee];
__device__ __align__(16) __half g_v[Bb*Hh*Ss*Ee];

// ---------------------------------------------------------------------------
// PTX helpers (compute_103-safe: mma.sync / ldmatrix / cp.async only)
// ---------------------------------------------------------------------------
__device__ __forceinline__ uint32_t smem_u32(const void* p) {
    uint32_t a;
    asm("{ .reg .u64 t; cvta.to.shared.u64 t, %1; cvt.u32.u64 %0, t; }"
        : "=r"(a) : "l"(p));
    return a;
}
__device__ __forceinline__ void ldsm4(uint32_t r[4], uint32_t addr) {
    asm volatile("ldmatrix.sync.aligned.m8n8.x4.shared.b16 {%0,%1,%2,%3}, [%4];"
        : "=r"(r[0]), "=r"(r[1]), "=r"(r[2]), "=r"(r[3]) : "r"(addr));
}
__device__ __forceinline__ void ldsm4t(uint32_t r[4], uint32_t addr) {
    asm volatile("ldmatrix.sync.aligned.m8n8.x4.trans.shared.b16 {%0,%1,%2,%3}, [%4];"
        : "=r"(r[0]), "=r"(r[1]), "=r"(r[2]), "=r"(r[3]) : "r"(addr));
}
__device__ __forceinline__ void mma16816(float d[4], const uint32_t a[4],
                                         uint32_t b0, uint32_t b1) {
    asm volatile(
        "mma.sync.aligned.m16n8k16.row.col.f32.f16.f16.f32 "
        "{%0,%1,%2,%3}, {%4,%5,%6,%7}, {%8,%9}, {%0,%1,%2,%3};"
        : "+f"(d[0]), "+f"(d[1]), "+f"(d[2]), "+f"(d[3])
        : "r"(a[0]), "r"(a[1]), "r"(a[2]), "r"(a[3]), "r"(b0), "r"(b1));
}
__device__ __forceinline__ float ex2f(float x) {
    float y; asm("ex2.approx.f32 %0, %1;" : "=f"(y) : "f"(x)); return y;
}
__device__ __forceinline__ uint32_t pack2h(float a, float b) {
    __half2 v = __floats2half2_rn(a, b);
    return *(uint32_t*)&v;
}
#define CP16(sa, ga) asm volatile("cp.async.cg.shared.global [%0], [%1], 16;" :: "r"(sa), "l"(ga))
#define CP_COMMIT()  asm volatile("cp.async.commit_group;" ::: "memory")
#define CP_WAIT1()   asm volatile("cp.async.wait_group 1;" ::: "memory")
#define CP_WAIT0()   asm volatile("cp.async.wait_group 0;" ::: "memory")

// ---------------------------------------------------------------------------
// Conversion kernels
// ---------------------------------------------------------------------------
__global__ void cvt_x(const float* __restrict__ x) {
    for (int i = blockIdx.x*blockDim.x + threadIdx.x; i < BS*Dd; i += gridDim.x*blockDim.x)
        g_x[i] = __float2half_rn(x[i]);
}
__global__ void cvt_wqkv(const float* __restrict__ Wq, const float* __restrict__ Wk,
                         const float* __restrict__ Wv) {
    for (int i = blockIdx.x*blockDim.x + threadIdx.x; i < NQKV*Dd; i += gridDim.x*blockDim.x) {
        int n = i / Dd, k = i - n * Dd;
        int which = n / (Hh*Ee);
        int rr = n - which * (Hh*Ee);
        int h = rr >> 6, e = rr & 63;
        const float* W = (which == 0) ? Wq : (which == 1) ? Wk : Wv;
        g_w[i] = __float2half_rn(W[(h*Dd + k)*Ee + e]);
    }
}
__global__ void cvt_wp(const float* __restrict__ Wp) {
    for (int i = blockIdx.x*blockDim.x + threadIdx.x; i < Dd*Dd; i += gridDim.x*blockDim.x) {
        int n = i / Dd, k = i - n * Dd;
        g_p[i] = __float2half_rn(Wp[k*Dd + n]);
    }
}

// ---------------------------------------------------------------------------
// GEMM via mma.sync fp16.  C[M][N] = A[M][K] * B[N][K]^T (+bias epilogue).
// CTA 128x128, 4 warps (2m x 2n), warp tile 64x64, K-chunk 32, 2-stage cp.async.
// MODE 0: QKV proj -> fp16 q/k/v (+bias). MODE 1: out proj fp32 (+bp via bq).
// ---------------------------------------------------------------------------
#define GST 40                        /* smem row stride in fp16 elems */
#define GT  (128*GST*2)               /* one tile: 10240 B */
#define GSTAGE (2*GT)                 /* A,B per stage: 20480 B */
#define GEMM_SMEM (2*GSTAGE)          /* 40960 B */
#define NCHUNK (Dd/32)                /* 24 */

template<int MODE>
__global__ __launch_bounds__(128, 2) void gemm_mma(
    const float* __restrict__ bq, const float* __restrict__ bk,
    const float* __restrict__ bv, float* __restrict__ outp)
{
    extern __shared__ char smem[];
    const uint32_t sbase = smem_u32(smem);

    const __half* __restrict__ Aa = (MODE == 0) ? g_x : g_a;
    const __half* __restrict__ Bw = (MODE == 0) ? g_w : g_p;

    const int m0 = blockIdx.x * 128;
    const int n0 = blockIdx.y * 128;
    const int tid  = threadIdx.x;
    const int wid  = tid >> 5, lane = tid & 31;
    const int wm = wid & 1, wn = wid >> 1;   // warp tile: rows wm*64, cols wn*64

    float acc[4][8][4] = {};                 // [mt][nf][4]

    auto issue = [&](int s) {
        const int buf = s & 1;
        const uint32_t sd = sbase + buf * GSTAGE;
        const int k0 = s * 32;
        #pragma unroll
        for (int it = 0; it < 4; it++) {
            int u = tid + it * 128;          // 0..511
            int r = u >> 2, c8 = (u & 3) * 8;
            uint32_t off = (uint32_t)(r * GST + c8) * 2;
            CP16(sd + 0*GT + off, Aa + (size_t)(m0 + r) * Dd + k0 + c8);
            CP16(sd + 1*GT + off, Bw + (size_t)(n0 + r) * Dd + k0 + c8);
        }
    };

    issue(0); CP_COMMIT();

    for (int s = 0; s < NCHUNK; s++) {
        if (s + 1 < NCHUNK) { issue(s + 1); CP_COMMIT(); CP_WAIT1(); }
        else                { CP_WAIT0(); }
        __syncthreads();

        const uint32_t sd = sbase + (s & 1) * GSTAGE;
        const uint32_t sA = sd, sB = sd + GT;

        #pragma unroll
        for (int kk = 0; kk < 2; kk++) {
            uint32_t af[4][4];
            uint32_t a_off = (uint32_t)((wm*64 + (lane & 15)) * GST + kk*16 + (lane >> 4)*8) * 2;
            #pragma unroll
            for (int mt = 0; mt < 4; mt++)
                ldsm4(af[mt], sA + a_off + mt*16*GST*2);

            uint32_t bf[8][2];
            uint32_t b_off = (uint32_t)((wn*64 + (lane & 15)) * GST + kk*16 + (lane >> 4)*8) * 2;
            #pragma unroll
            for (int half = 0; half < 4; half++) {
                uint32_t t[4];
                ldsm4(t, sB + b_off + half*16*GST*2);
                bf[half*2+0][0] = t[0]; bf[half*2+0][1] = t[2];
                bf[half*2+1][0] = t[1]; bf[half*2+1][1] = t[3];
            }
            #pragma unroll
            for (int mt = 0; mt < 4; mt++)
                #pragma unroll
                for (int nf = 0; nf < 8; nf++)
                    mma16816(acc[mt][nf], af[mt], bf[nf][0], bf[nf][1]);
        }
        __syncthreads();
    }

    // ---- epilogue ----
    #pragma unroll
    for (int mt = 0; mt < 4; mt++) {
        const int m = m0 + wm*64 + mt*16 + (lane >> 2);
        #pragma unroll
        for (int nf = 0; nf < 8; nf++) {
            if (MODE == 0) {
                int ng = n0 + wn*64 + nf*8;
                int which = ng / (Hh*Ee);
                int rr = ng - which * (Hh*Ee);
                int h = rr >> 6;
                int e0 = (rr & 63) + (lane & 3)*2;
                const float* bsrc = (which == 0) ? bq : (which == 1) ? bk : bv;
                float b0f = bsrc[h*Ee + e0], b1f = bsrc[h*Ee + e0 + 1];
                int b = m >> 11, sI = m & 2047;
                size_t base = (((size_t)(b*Hh + h)) * Ss + sI) * Ee + e0;
                __half* dst = (which == 0) ? g_q : (which == 1) ? g_k : g_v;
                *(uint32_t*)(dst + base) =
                    pack2h(acc[mt][nf][0] + b0f, acc[mt][nf][1] + b1f);
                *(uint32_t*)(dst + base + 8*Ee) =
                    pack2h(acc[mt][nf][2] + b0f, acc[mt][nf][3] + b1f);
            } else {
                int nn = n0 + wn*64 + nf*8 + (lane & 3)*2;
                float b0f = bq[nn], b1f = bq[nn + 1];   // bq carries bp
                float2 v0 = { acc[mt][nf][0] + b0f, acc[mt][nf][1] + b1f };
                float2 v1 = { acc[mt][nf][2] + b0f, acc[mt][nf][3] + b1f };
                *(float2*)(outp + (size_t)m*Dd + nn)       = v0;
                *(float2*)(outp + (size_t)(m+8)*Dd + nn)   = v1;
            }
        }
    }
}

// ---------------------------------------------------------------------------
// Flash attention, register-resident softmax, single fp16.
// CTA: 128 q-rows, 128 threads (4 warps x 32 q-rows x all 64 keys).
// K/V double-buffered via cp.async; Q fragments in regs.
// ---------------------------------------------------------------------------
#define AST 72                 /* fp16 row stride (64+8) */
#define SUBB (64*AST*2)        /* one 64x64 fp16 subtile: 9216 B */
#define STG (2*SUBB)           /* stage: K,V = 18432 B */
#define QB  (128*AST*2)        /* 128x64 Q array: 18432 B */
#define OFF_Q (2*STG)          /* 36864 */
#define ATTN_SMEM (OFF_Q + QB) /* 55296 B */

__global__ __launch_bounds__(128) void attn_mma()
{
    extern __shared__ char smem[];
    const uint32_t sbase = smem_u32(smem);
    const int q0 = blockIdx.x * 128;
    const int h  = blockIdx.y;
    const int b  = blockIdx.z;
    const int tid = threadIdx.x;
    const int wid = tid >> 5, lane = tid & 31;
    const size_t gbase = (size_t)(b*Hh + h) * Ss * Ee;
    const __half* __restrict__ qp = g_q + gbase;
    const __half* __restrict__ kp = g_k + gbase;
    const __half* __restrict__ vp = g_v + gbase;

    // ---- stage Q (128 rows x 64 cols = 8 x 16B chunks per row) ----
    #pragma unroll
    for (int i = 0; i < 8; i++) {
        int rem = i*128 + tid;            // 0..1023
        int r = rem >> 3, c16 = rem & 7;
        CP16(sbase + OFF_Q + (uint32_t)r*(AST*2) + c16*16, qp + (q0 + r)*Ee + c16*8);
    }
    CP_COMMIT();

    // ---- prefetch KV tile 0 into stage 0 ----
    #pragma unroll
    for (int i = 0; i < 8; i++) {
        int sub = i >> 2;                 // 0 K, 1 V
        int rem = (i & 3)*128 + tid;
        int r = rem >> 3, c16 = rem & 7;
        const __half* gp = (sub == 0 ? kp : vp) + r*Ee + c16*8;
        CP16(sbase + sub*SUBB + (uint32_t)r*(AST*2) + c16*16, gp);
    }
    CP_COMMIT();

    CP_WAIT1();            // Q ready (KV0 may still be in flight)
    __syncthreads();

    // ---- Q fragments in regs (2 msub x 4 k16) ----
    uint32_t qh[2][4][4];
    #pragma unroll
    for (int ms = 0; ms < 2; ms++) {
        uint32_t qo = (uint32_t)(wid*32 + ms*16 + (lane & 15))*(AST*2) + (lane >> 4)*16;
        #pragma unroll
        for (int kk = 0; kk < 4; kk++)
            ldsm4(qh[ms][kk], sbase + OFF_Q + qo + kk*32);
    }
    __syncthreads();

    float o[2][8][4] = {};
    float mm[2][2], ll[2][2];
    #pragma unroll
    for (int ms = 0; ms < 2; ms++) { mm[ms][0] = mm[ms][1] = -1e30f; ll[ms][0] = ll[ms][1] = 0.f; }
    const float Cc = 0.18033688011112042f;   // 0.125 * log2(e)

    for (int s = 0; s < Ss/64; s++) {
        if (s + 1 < Ss/64) {
            const uint32_t stn = sbase + ((s+1) & 1)*STG;
            const int k0 = (s+1)*64;
            #pragma unroll
            for (int i = 0; i < 8; i++) {
                int sub = i >> 2;
                int rem = (i & 3)*128 + tid;
                int r = rem >> 3, c16 = rem & 7;
                const __half* gp = (sub == 0 ? kp : vp) + (k0 + r)*Ee + c16*8;
                CP16(stn + sub*SUBB + (uint32_t)r*(AST*2) + c16*16, gp);
            }
            CP_COMMIT();
            CP_WAIT1();
        } else {
            CP_WAIT0();
        }
        __syncthreads();

        const uint32_t st = sbase + (s & 1)*STG;

        // ---- S = Q K^T ----
        float sacc[2][8][4];
        #pragma unroll
        for (int ms = 0; ms < 2; ms++)
            #pragma unroll
            for (int nf = 0; nf < 8; nf++)
                #pragma unroll
                for (int j = 0; j < 4; j++) sacc[ms][nf][j] = 0.f;

        uint32_t kbase = (uint32_t)(lane & 15)*(AST*2) + (lane >> 4)*16;
        #pragma unroll
        for (int kk = 0; kk < 4; kk++) {
            #pragma unroll
            for (int g = 0; g < 4; g++) {
                uint32_t th[4];
                ldsm4(th, st + kbase + (uint32_t)g*16*(AST*2) + kk*32);
                #pragma unroll
                for (int ms = 0; ms < 2; ms++) {
                    mma16816(sacc[ms][2*g],   qh[ms][kk], th[0], th[2]);
                    mma16816(sacc[ms][2*g+1], qh[ms][kk], th[1], th[3]);
                }
            }
        }

        // ---- online softmax (registers; rows warp-local) + P frags ----
        uint32_t pf[2][4][4];
        float al[2][2];
        #pragma unroll
        for (int ms = 0; ms < 2; ms++) {
            float r0 = -1e30f, r1 = -1e30f;
            #pragma unroll
            for (int nf = 0; nf < 8; nf++) {
                r0 = fmaxf(r0, fmaxf(sacc[ms][nf][0], sacc[ms][nf][1]));
                r1 = fmaxf(r1, fmaxf(sacc[ms][nf][2], sacc[ms][nf][3]));
            }
            r0 = fmaxf(r0, __shfl_xor_sync(0xffffffffu, r0, 1));
            r0 = fmaxf(r0, __shfl_xor_sync(0xffffffffu, r0, 2));
            r1 = fmaxf(r1, __shfl_xor_sync(0xffffffffu, r1, 1));
            r1 = fmaxf(r1, __shfl_xor_sync(0xffffffffu, r1, 2));
            float mn0 = fmaxf(mm[ms][0], r0), mn1 = fmaxf(mm[ms][1], r1);
            al[ms][0] = ex2f((mm[ms][0] - mn0)*Cc);
            al[ms][1] = ex2f((mm[ms][1] - mn1)*Cc);
            mm[ms][0] = mn0; mm[ms][1] = mn1;

            float ps0 = 0.f, ps1 = 0.f;
            #pragma unroll
            for (int nf = 0; nf < 8; nf++) {
                sacc[ms][nf][0] = ex2f((sacc[ms][nf][0] - mn0)*Cc);
                sacc[ms][nf][1] = ex2f((sacc[ms][nf][1] - mn0)*Cc);
                sacc[ms][nf][2] = ex2f((sacc[ms][nf][2] - mn1)*Cc);
                sacc[ms][nf][3] = ex2f((sacc[ms][nf][3] - mn1)*Cc);
                ps0 += sacc[ms][nf][0] + sacc[ms][nf][1];
                ps1 += sacc[ms][nf][2] + sacc[ms][nf][3];
            }
            ps0 += __shfl_xor_sync(0xffffffffu, ps0, 1);
            ps0 += __shfl_xor_sync(0xffffffffu, ps0, 2);
            ps1 += __shfl_xor_sync(0xffffffffu, ps1, 1);
            ps1 += __shfl_xor_sync(0xffffffffu, ps1, 2);
            ll[ms][0] = ll[ms][0]*al[ms][0] + ps0;
            ll[ms][1] = ll[ms][1]*al[ms][1] + ps1;

            #pragma unroll
            for (int kk = 0; kk < 4; kk++) {
                int n0f = 2*kk, n1f = 2*kk + 1;
                pf[ms][kk][0] = pack2h(sacc[ms][n0f][0], sacc[ms][n0f][1]);
                pf[ms][kk][1] = pack2h(sacc[ms][n0f][2], sacc[ms][n0f][3]);
                pf[ms][kk][2] = pack2h(sacc[ms][n1f][0], sacc[ms][n1f][1]);
                pf[ms][kk][3] = pack2h(sacc[ms][n1f][2], sacc[ms][n1f][3]);
            }
        }

        // ---- rescale O, then O += P V ----
        #pragma unroll
        for (int ms = 0; ms < 2; ms++)
            #pragma unroll
            for (int nf = 0; nf < 8; nf++) {
                o[ms][nf][0] *= al[ms][0]; o[ms][nf][1] *= al[ms][0];
                o[ms][nf][2] *= al[ms][1]; o[ms][nf][3] *= al[ms][1];
            }
        #pragma unroll
        for (int kk = 0; kk < 4; kk++) {
            uint32_t vb = st + SUBB + (uint32_t)(kk*16 + (lane & 15))*(AST*2)
                          + (lane >> 4)*16;
            #pragma unroll
            for (int g = 0; g < 4; g++) {          // e16 groups
                uint32_t th[4];
                ldsm4t(th, vb + g*32);
                #pragma unroll
                for (int ms = 0; ms < 2; ms++) {
                    mma16816(o[ms][2*g],   pf[ms][kk], th[0], th[1]);
                    mma16816(o[ms][2*g+1], pf[ms][kk], th[2], th[3]);
                }
            }
        }
        __syncthreads();   // stage fully consumed before next iter's issue
    }

    // ---- normalize + store fp16 (feeds proj GEMM) ----
    #pragma unroll
    for (int ms = 0; ms < 2; ms++) {
        const int r0i = wid*32 + ms*16 + (lane >> 2);
        float inv0 = 1.0f / ll[ms][0], inv1 = 1.0f / ll[ms][1];
        #pragma unroll
        for (int nf = 0; nf < 8; nf++) {
            int e = nf*8 + (lane & 3)*2;
            size_t i0 = ((size_t)(b*Ss + q0 + r0i)*Hh + h)*Ee + e;
            size_t i1 = i0 + (size_t)8*Hh*Ee;
            *(uint32_t*)(g_a + i0) = pack2h(o[ms][nf][0]*inv0, o[ms][nf][1]*inv0);
            *(uint32_t*)(g_a + i1) = pack2h(o[ms][nf][2]*inv1, o[ms][nf][3]*inv1);
        }
    }
}

// ---------------------------------------------------------------------------
extern "C" void kernel_launch(void* const* d_in, const int* in_sizes, int n_in,
                              void* d_out, int out_size)
{
    const float* x  = (const float*)d_in[0];
    const float* Wq = (const float*)d_in[1];
    const float* bq = (const float*)d_in[2];
    const float* Wk = (const float*)d_in[3];
    const float* bk = (const float*)d_in[4];
    const float* Wv = (const float*)d_in[5];
    const float* bv = (const float*)d_in[6];
    const float* Wp = (const float*)d_in[7];
    const float* bp = (const float*)d_in[8];
    float* out = (float*)d_out;

    cudaFuncSetAttribute(gemm_mma<0>, cudaFuncAttributeMaxDynamicSharedMemorySize, GEMM_SMEM);
    cudaFuncSetAttribute(gemm_mma<1>, cudaFuncAttributeMaxDynamicSharedMemorySize, GEMM_SMEM);
    cudaFuncSetAttribute(attn_mma,    cudaFuncAttributeMaxDynamicSharedMemorySize, ATTN_SMEM);

    cvt_x<<<2048, 256>>>(x);
    cvt_wqkv<<<1024, 256>>>(Wq, Wk, Wv);
    gemm_mma<0><<<dim3(BS/128, NQKV/128), 128, GEMM_SMEM>>>(bq, bk, bv, nullptr);
    attn_mma<<<dim3(Ss/128, Hh, Bb), 128, ATTN_SMEM>>>();
    cvt_wp<<<512, 256>>>(Wp);
    gemm_mma<1><<<dim3(BS/128, Dd/128), 128, GEMM_SMEM>>>(bp, nullptr, nullptr, out);
}